// round 2
// baseline (speedup 1.0000x reference)
#include <cuda_runtime.h>
#include <math.h>

#define Bb 256
#define Tt 60
#define Cc 512
#define Ee 10
#define Kk 5
#define Hh 8
#define DH 64

// ---------------- scratch (device globals; no allocation allowed) ----------------
__device__ float g_q[Bb * Cc];          // scaled q projection (B, H*DH)
__device__ float g_rk[Bb * Hh * Cc];    // q @ Wk per head      (B,H,C)
__device__ float g_qb[Bb * Hh];         // q . bk per head
__device__ float g_ctx[Bb * Cc];        // attention context
__device__ float g_tmp[Bb * Cc];        // temp_w
__device__ int   g_topk_i[Bb * Kk];
__device__ float g_topk_p[Bb * Kk];
__device__ float g_tw[Bb * Kk * Tt];    // normalized time weights
__device__ float g_sw[Bb * Kk];         // sum of time weights
__device__ float g_pooled[Bb * Kk * 256]; // pooled hidden (after relu+time pool)
__device__ float g_w2t[Ee * 256 * Cc];  // exp_w2 transposed to [E][j][c]

// ---------------- helpers ----------------
__device__ __forceinline__ float softplus_f(float x) {
    return fmaxf(x, 0.0f) + log1pf(expf(-fabsf(x)));
}

// ---------------- W2 transpose: [E][C][256] -> [E][256][C] ----------------
__global__ void transpose_w2_kernel(const float* __restrict__ w2) {
    __shared__ float t[32][33];
    int e = blockIdx.z;
    int j0 = blockIdx.x * 32;
    int c0 = blockIdx.y * 32;
    int tx = threadIdx.x, ty = threadIdx.y; // 32 x 8
#pragma unroll
    for (int r = 0; r < 4; r++) {
        int c = c0 + ty + r * 8;
        t[ty + r * 8][tx] = w2[(e * Cc + c) * 256 + j0 + tx];
    }
    __syncthreads();
#pragma unroll
    for (int r = 0; r < 4; r++) {
        int j = j0 + ty + r * 8;
        g_w2t[(e * 256 + j) * Cc + c0 + tx] = t[tx][ty + r * 8];
    }
}

// ---------------- generic small SGEMM: C[M,512] = alpha*(A[M,512] @ W[512,512]^T + bias) ----------------
// grid (N/64, M/64), 256 threads, 64x64x16 tiles, 4x4 per thread
__global__ void sgemm_bias_kernel(const float* __restrict__ A,
                                  const float* __restrict__ W,
                                  const float* __restrict__ bias,
                                  float* __restrict__ Cout,
                                  float alpha) {
    __shared__ float As[16 * 68];
    __shared__ float Ws[16 * 68];
    int n0 = blockIdx.x * 64;
    int m0 = blockIdx.y * 64;
    int tid = threadIdx.x;
    int ty = tid >> 4, tx = tid & 15;
    float acc[4][4] = {};
    for (int kk = 0; kk < 512; kk += 16) {
#pragma unroll
        for (int r = 0; r < 4; r++) {
            int l = tid + 256 * r;
            int m = l >> 4, kc = l & 15;
            As[kc * 68 + m] = A[(m0 + m) * 512 + kk + kc];
            Ws[kc * 68 + m] = W[(n0 + m) * 512 + kk + kc];
        }
        __syncthreads();
#pragma unroll
        for (int kc = 0; kc < 16; kc++) {
            float4 av = *(const float4*)&As[kc * 68 + ty * 4];
            float4 bv = *(const float4*)&Ws[kc * 68 + tx * 4];
            float a[4] = {av.x, av.y, av.z, av.w};
            float b[4] = {bv.x, bv.y, bv.z, bv.w};
#pragma unroll
            for (int i = 0; i < 4; i++)
#pragma unroll
                for (int j = 0; j < 4; j++) acc[i][j] += a[i] * b[j];
        }
        __syncthreads();
    }
#pragma unroll
    for (int i = 0; i < 4; i++) {
        int m = m0 + ty * 4 + i;
#pragma unroll
        for (int j = 0; j < 4; j++) {
            int n = n0 + tx * 4 + j;
            Cout[m * 512 + n] = alpha * (acc[i][j] + bias[n]);
        }
    }
}

// ---------------- rk[b,h,:] = q[b,h,:] @ Wk_h ; qb = q . bk_h ----------------
__global__ void rk_kernel(const float* __restrict__ in_proj_w,
                          const float* __restrict__ in_proj_b) {
    int b = blockIdx.x / Hh, h = blockIdx.x % Hh;
    __shared__ float q_s[64];
    int tid = threadIdx.x; // 128
    if (tid < 64) q_s[tid] = g_q[b * Cc + h * 64 + tid];
    __syncthreads();
    float acc[4] = {0.f, 0.f, 0.f, 0.f};
    const float* wb = in_proj_w + (512 + h * 64) * 512;
#pragma unroll 4
    for (int d = 0; d < 64; d++) {
        float qd = q_s[d];
#pragma unroll
        for (int r = 0; r < 4; r++) acc[r] += qd * wb[d * 512 + tid + r * 128];
    }
#pragma unroll
    for (int r = 0; r < 4; r++) g_rk[(b * Hh + h) * Cc + tid + r * 128] = acc[r];
    if (tid == 0) {
        float s = 0.f;
        for (int d = 0; d < 64; d++) s += q_s[d] * in_proj_b[512 + h * 64 + d];
        g_qb[b * Hh + h] = s;
    }
}

// ---------------- attention: scores -> softmax -> pooled data -> ctx ----------------
__global__ void attn_kernel(const float* __restrict__ data,
                            const float* __restrict__ in_proj_w,
                            const float* __restrict__ in_proj_b) {
    int b = blockIdx.x / Hh, h = blockIdx.x % Hh;
    __shared__ float rk_s[512];
    __shared__ float pr[64];
    __shared__ float pd_s[512];
    int tid = threadIdx.x; // 128
    for (int c = tid; c < 512; c += 128) rk_s[c] = g_rk[(b * Hh + h) * Cc + c];
    __syncthreads();
    int w = tid >> 5, lane = tid & 31;
    float qb = g_qb[b * Hh + h];
    // scores: warp w handles 15 t's
    for (int ti = 0; ti < 15; ti++) {
        int t = w * 15 + ti;
        const float* dp = data + (b * Tt + t) * Cc;
        float sum = 0.f;
        for (int c = lane; c < 512; c += 32) sum += dp[c] * rk_s[c];
#pragma unroll
        for (int o = 16; o > 0; o >>= 1) sum += __shfl_down_sync(0xffffffffu, sum, o);
        if (lane == 0) pr[t] = sum + qb;
    }
    __syncthreads();
    if (tid == 0) {
        float m = pr[0];
        for (int t = 1; t < Tt; t++) m = fmaxf(m, pr[t]);
        float s = 0.f;
        for (int t = 0; t < Tt; t++) { float e = expf(pr[t] - m); pr[t] = e; s += e; }
        float inv = 1.0f / s;
        for (int t = 0; t < Tt; t++) pr[t] *= inv;
    }
    __syncthreads();
    // pooled data: pd[c] = sum_t p[t]*data[b,t,c]
    for (int c = tid; c < 512; c += 128) {
        float a = 0.f;
        const float* dp = data + b * Tt * Cc + c;
#pragma unroll 4
        for (int t = 0; t < Tt; t++) a += pr[t] * dp[t * Cc];
        pd_s[c] = a;
    }
    __syncthreads();
    // ctx[d] = pd . Wv_row(d) + bv[d]
    for (int di = 0; di < 16; di++) {
        int d = w * 16 + di;
        const float* wr = in_proj_w + (1024 + h * 64 + d) * 512;
        float sum = 0.f;
        for (int c = lane; c < 512; c += 32) sum += wr[c] * pd_s[c];
#pragma unroll
        for (int o = 16; o > 0; o >>= 1) sum += __shfl_down_sync(0xffffffffu, sum, o);
        if (lane == 0) g_ctx[b * Cc + h * 64 + d] = sum + in_proj_b[1024 + h * 64 + d];
    }
}

// ---------------- router + top-k + beta time weights (per b) ----------------
__global__ void router_kernel(const float* __restrict__ router_w,
                              const float* __restrict__ router_b,
                              const float* __restrict__ beta_w,
                              const float* __restrict__ beta_b) {
    int b = blockIdx.x;
    __shared__ float tmp_s[512];
    __shared__ float logit[32];
    __shared__ float al[Ee], be[Ee];
    __shared__ int sel_i[Kk];
    __shared__ float w_s[Kk * Tt];
    int tid = threadIdx.x; // 256
    for (int c = tid; c < 512; c += 256) tmp_s[c] = g_tmp[b * Cc + c];
    __syncthreads();
    int w = tid >> 5, lane = tid & 31;
    for (int r = w; r < 30; r += 8) {
        const float* wr; float bias;
        if (r < Ee) { wr = router_w + r * 512; bias = router_b[r]; }
        else { wr = beta_w + (r - Ee) * 512; bias = beta_b[r - Ee]; }
        float s = 0.f;
        for (int c = lane; c < 512; c += 32) s += wr[c] * tmp_s[c];
#pragma unroll
        for (int o = 16; o > 0; o >>= 1) s += __shfl_down_sync(0xffffffffu, s, o);
        if (lane == 0) logit[r] = s + bias;
    }
    __syncthreads();
    if (tid < Ee) {
        al[tid] = softplus_f(logit[Ee + 2 * tid]) + 1e-6f;
        be[tid] = softplus_f(logit[Ee + 2 * tid + 1]) + 1e-6f;
    }
    if (tid == 0) {
        float m = logit[0];
        for (int e = 1; e < Ee; e++) m = fmaxf(m, logit[e]);
        float pe[Ee]; float s = 0.f;
        for (int e = 0; e < Ee; e++) { pe[e] = expf(logit[e] - m); s += pe[e]; }
        float invs = 1.0f / s;
        for (int e = 0; e < Ee; e++) pe[e] *= invs;
        bool used[Ee] = {};
        float psum = 0.f; float sp[Kk];
        for (int kk = 0; kk < Kk; kk++) {
            int best = 0; float bv = -1.f;
            for (int e = 0; e < Ee; e++)
                if (!used[e] && pe[e] > bv) { bv = pe[e]; best = e; }
            used[best] = true; sel_i[kk] = best; sp[kk] = bv; psum += bv;
        }
        float inv = 1.0f / (psum + 1e-8f);
        for (int kk = 0; kk < Kk; kk++) {
            g_topk_i[b * Kk + kk] = sel_i[kk];
            g_topk_p[b * Kk + kk] = sp[kk] * inv;
        }
    }
    __syncthreads();
    // FIX: Kk*Tt = 300 > blockDim (256); use a strided loop so all 300
    // (k,t) pairs are computed (previously w_s[256..299] was uninitialized).
    for (int i = tid; i < Kk * Tt; i += 256) {
        int kk = i / Tt, t = i % Tt;
        int e = sel_i[kk];
        float a = al[e], bb = be[e];
        float tt = (float)t / 59.0f;
        float lt = logf(tt + 1e-12f);
        float l1 = logf(1.0f - tt + 1e-12f);
        float norm = lgammaf(a) + lgammaf(bb) - lgammaf(a + bb);
        w_s[i] = expf((a - 1.0f) * lt + (bb - 1.0f) * l1 - norm);
    }
    __syncthreads();
    if (tid < Kk) {
        float m = 0.f;
        for (int t = 0; t < Tt; t++) m = fmaxf(m, w_s[tid * Tt + t]);
        float inv = 1.0f / (m + 1e-8f);
        float s = 0.f;
        for (int t = 0; t < Tt; t++) {
            float v = w_s[tid * Tt + t] * inv;
            g_tw[(b * Kk + tid) * Tt + t] = v;
            s += v;
        }
        g_sw[b * Kk + tid] = s;
    }
}

// ---------------- layer1 + relu + time-weighted pool (the big GEMM) ----------------
// grid (4, B*K) : each block does 64 output features for one (b,k)
__global__ void layer1_pool_kernel(const float* __restrict__ data,
                                   const float* __restrict__ w1,
                                   const float* __restrict__ b1) {
    __shared__ float As[16 * 68];
    __shared__ float Ws[16 * 68];
    __shared__ float tw_s[64];
    __shared__ float red[16 * 68];
    int bk = blockIdx.y;
    int b = bk / Kk, k = bk % Kk;
    int n0 = blockIdx.x * 64;
    int e = g_topk_i[b * Kk + k];
    const float* A = data + b * Tt * Cc;                    // 60 x 512
    const float* Wt = w1 + e * 256 * 512 + n0 * 512;        // 64 x 512 slice
    int tid = threadIdx.x;
    if (tid < 64) tw_s[tid] = (tid < Tt) ? g_tw[bk * Tt + tid] : 0.0f;
    int ty = tid >> 4, tx = tid & 15;
    float acc[4][4] = {};
    for (int kk = 0; kk < 512; kk += 16) {
#pragma unroll
        for (int r = 0; r < 4; r++) {
            int l = tid + 256 * r;
            int m = l >> 4, kc = l & 15;
            As[kc * 68 + m] = (m < Tt) ? A[m * 512 + kk + kc] : 0.0f;
            Ws[kc * 68 + m] = Wt[m * 512 + kk + kc];
        }
        __syncthreads();
#pragma unroll
        for (int kc = 0; kc < 16; kc++) {
            float4 av = *(const float4*)&As[kc * 68 + ty * 4];
            float4 bv = *(const float4*)&Ws[kc * 68 + tx * 4];
            float a[4] = {av.x, av.y, av.z, av.w};
            float bq[4] = {bv.x, bv.y, bv.z, bv.w};
#pragma unroll
            for (int i = 0; i < 4; i++)
#pragma unroll
                for (int j = 0; j < 4; j++) acc[i][j] += a[i] * bq[j];
        }
        __syncthreads();
    }
    // epilogue: relu(acc + b1) weighted by time weight, reduced over t
    float s[4] = {0.f, 0.f, 0.f, 0.f};
#pragma unroll
    for (int i = 0; i < 4; i++) {
        float wv = tw_s[ty * 4 + i];
#pragma unroll
        for (int j = 0; j < 4; j++) {
            float h = acc[i][j] + b1[e * 256 + n0 + tx * 4 + j];
            h = fmaxf(h, 0.0f);
            s[j] += wv * h;
        }
    }
    *(float4*)&red[ty * 68 + tx * 4] = make_float4(s[0], s[1], s[2], s[3]);
    __syncthreads();
    for (int st = 8; st > 0; st >>= 1) {
        if (ty < st) {
#pragma unroll
            for (int j = 0; j < 4; j++)
                red[ty * 68 + tx * 4 + j] += red[(ty + st) * 68 + tx * 4 + j];
        }
        __syncthreads();
    }
    if (ty == 0) {
#pragma unroll
        for (int j = 0; j < 4; j++)
            g_pooled[bk * 256 + n0 + tx * 4 + j] = red[tx * 4 + j];
    }
}

// ---------------- layer2 + router combine + LayerNorm (per b) ----------------
__global__ void final_kernel(const float* __restrict__ b2,
                             const float* __restrict__ ln_g,
                             const float* __restrict__ ln_b,
                             float* __restrict__ out) {
    int b = blockIdx.x;
    int tid = threadIdx.x; // 256
    __shared__ float sp[256];
    __shared__ float red[18];
    float y0 = 0.f, y1 = 0.f;
    int c0 = tid, c1 = tid + 256;
    for (int kk = 0; kk < Kk; kk++) {
        int e = g_topk_i[b * Kk + kk];
        float p = g_topk_p[b * Kk + kk];
        float sw = g_sw[b * Kk + kk];
        __syncthreads();
        sp[tid] = g_pooled[(b * Kk + kk) * 256 + tid];
        __syncthreads();
        float a0 = 0.f, a1 = 0.f;
        const float* wt = g_w2t + e * 256 * Cc;
#pragma unroll 4
        for (int j = 0; j < 256; j++) {
            float sv = sp[j];
            a0 += sv * wt[j * Cc + c0];
            a1 += sv * wt[j * Cc + c1];
        }
        y0 += p * (a0 + sw * b2[e * Cc + c0]);
        y1 += p * (a1 + sw * b2[e * Cc + c1]);
    }
    // LayerNorm over 512
    float s = y0 + y1, sq = y0 * y0 + y1 * y1;
    int w = tid >> 5, lane = tid & 31;
#pragma unroll
    for (int o = 16; o > 0; o >>= 1) {
        s += __shfl_down_sync(0xffffffffu, s, o);
        sq += __shfl_down_sync(0xffffffffu, sq, o);
    }
    if (lane == 0) { red[w] = s; red[8 + w] = sq; }
    __syncthreads();
    if (tid == 0) {
        float S = 0.f, SQ = 0.f;
        for (int i = 0; i < 8; i++) { S += red[i]; SQ += red[8 + i]; }
        red[16] = S; red[17] = SQ;
    }
    __syncthreads();
    float mean = red[16] * (1.0f / 512.0f);
    float var = red[17] * (1.0f / 512.0f) - mean * mean;
    float rstd = rsqrtf(var + 1e-5f);
    out[b * Cc + c0] = (y0 - mean) * rstd * ln_g[c0] + ln_b[c0];
    out[b * Cc + c1] = (y1 - mean) * rstd * ln_g[c1] + ln_b[c1];
}

// ---------------- launch ----------------
extern "C" void kernel_launch(void* const* d_in, const int* in_sizes, int n_in,
                              void* d_out, int out_size) {
    const float* qst = (const float*)d_in[0];
    const float* data = (const float*)d_in[1];
    const float* ipw = (const float*)d_in[2];
    const float* ipb = (const float*)d_in[3];
    const float* opw = (const float*)d_in[4];
    const float* opb = (const float*)d_in[5];
    const float* rw  = (const float*)d_in[6];
    const float* rb  = (const float*)d_in[7];
    const float* bw  = (const float*)d_in[8];
    const float* bb  = (const float*)d_in[9];
    const float* w1  = (const float*)d_in[10];
    const float* b1  = (const float*)d_in[11];
    const float* w2  = (const float*)d_in[12];
    const float* b2  = (const float*)d_in[13];
    const float* lng = (const float*)d_in[14];
    const float* lnb = (const float*)d_in[15];
    float* out = (float*)d_out;

    float *p_q, *p_ctx, *p_tmp;
    cudaGetSymbolAddress((void**)&p_q, g_q);
    cudaGetSymbolAddress((void**)&p_ctx, g_ctx);
    cudaGetSymbolAddress((void**)&p_tmp, g_tmp);

    transpose_w2_kernel<<<dim3(8, 16, 10), dim3(32, 8)>>>(w2);
    // q projection: (256,512) @ Wq^T + bq, scaled by 1/sqrt(DH)=0.125
    sgemm_bias_kernel<<<dim3(8, 4), 256>>>(qst, ipw, ipb, p_q, 0.125f);
    rk_kernel<<<Bb * Hh, 128>>>(ipw, ipb);
    attn_kernel<<<Bb * Hh, 128>>>(data, ipw, ipb);
    // temp_w = ctx @ out_proj_w^T + b
    sgemm_bias_kernel<<<dim3(8, 4), 256>>>(p_ctx, opw, opb, p_tmp, 1.0f);
    router_kernel<<<Bb, 256>>>(rw, rb, bw, bb);
    layer1_pool_kernel<<<dim3(4, Bb * Kk), 256>>>(data, w1, b1);
    final_kernel<<<Bb, 256>>>(b2, lng, lnb, out);
}

// round 4
// speedup vs baseline: 1.3616x; 1.3616x over previous
#include <cuda_runtime.h>
#include <cuda_bf16.h>
#include <cstdint>
#include <math.h>

#define Bb 256
#define Tt 60
#define Cc 512
#define Ee 10
#define Kk 5
#define Hh 8
#define DH 64

// ---------------- scratch (device globals; no allocation allowed) ----------------
__device__ float g_q[Bb * Cc];
__device__ float g_rk[Bb * Hh * Cc];
__device__ float g_qb[Bb * Hh];
__device__ float g_ctx[Bb * Cc];
__device__ float g_tmp[Bb * Cc];
__device__ int   g_topk_i[Bb * Kk];
__device__ float g_topk_p[Bb * Kk];
__device__ float g_tw[Bb * Kk * Tt];
__device__ float g_sw[Bb * Kk];
__device__ float g_pooled[Bb * Kk * 256];
__device__ float g_w2t[Ee * 256 * Cc];
// bf16 hi/lo splits for tensor-core layer1
__device__ __nv_bfloat16 g_dhi[Bb * Tt * Cc];
__device__ __nv_bfloat16 g_dlo[Bb * Tt * Cc];
__device__ __nv_bfloat16 g_w1hi[Ee * 256 * Cc];
__device__ __nv_bfloat16 g_w1lo[Ee * 256 * Cc];

// ---------------- helpers ----------------
__device__ __forceinline__ float softplus_f(float x) {
    return fmaxf(x, 0.0f) + log1pf(expf(-fabsf(x)));
}
__device__ __forceinline__ uint32_t smem_u32(const void* p) {
    return (uint32_t)__cvta_generic_to_shared(p);
}
__device__ __forceinline__ void ldm_x4(uint32_t* r, uint32_t addr) {
    asm volatile("ldmatrix.sync.aligned.m8n8.x4.shared.b16 {%0,%1,%2,%3}, [%4];"
                 : "=r"(r[0]), "=r"(r[1]), "=r"(r[2]), "=r"(r[3]) : "r"(addr));
}
__device__ __forceinline__ void mma16816(float* c, const uint32_t* a, const uint32_t* b) {
    asm volatile(
        "mma.sync.aligned.m16n8k16.row.col.f32.bf16.bf16.f32 "
        "{%0,%1,%2,%3}, {%4,%5,%6,%7}, {%8,%9}, {%0,%1,%2,%3};"
        : "+f"(c[0]), "+f"(c[1]), "+f"(c[2]), "+f"(c[3])
        : "r"(a[0]), "r"(a[1]), "r"(a[2]), "r"(a[3]), "r"(b[0]), "r"(b[1]));
}

// ---------------- fp32 -> (bf16 hi, bf16 lo) splits (write device globals directly) ----------------
__global__ void split_data_kernel(const float* __restrict__ x) {
    int i = blockIdx.x * 256 + threadIdx.x;
    if (i < Bb * Tt * Cc) {
        float v = x[i];
        __nv_bfloat16 h = __float2bfloat16(v);
        g_dhi[i] = h;
        g_dlo[i] = __float2bfloat16(v - __bfloat162float(h));
    }
}
__global__ void split_w1_kernel(const float* __restrict__ x) {
    int i = blockIdx.x * 256 + threadIdx.x;
    if (i < Ee * 256 * Cc) {
        float v = x[i];
        __nv_bfloat16 h = __float2bfloat16(v);
        g_w1hi[i] = h;
        g_w1lo[i] = __float2bfloat16(v - __bfloat162float(h));
    }
}

// ---------------- W2 transpose: [E][C][256] -> [E][256][C] ----------------
__global__ void transpose_w2_kernel(const float* __restrict__ w2) {
    __shared__ float t[32][33];
    int e = blockIdx.z;
    int j0 = blockIdx.x * 32;
    int c0 = blockIdx.y * 32;
    int tx = threadIdx.x, ty = threadIdx.y;
#pragma unroll
    for (int r = 0; r < 4; r++) {
        int c = c0 + ty + r * 8;
        t[ty + r * 8][tx] = w2[(e * Cc + c) * 256 + j0 + tx];
    }
    __syncthreads();
#pragma unroll
    for (int r = 0; r < 4; r++) {
        int j = j0 + ty + r * 8;
        g_w2t[(e * 256 + j) * Cc + c0 + tx] = t[tx][ty + r * 8];
    }
}

// ---------------- generic small SGEMM body (device fn) ----------------
__device__ __forceinline__ void sgemm_body(const float* __restrict__ A,
                                           const float* __restrict__ W,
                                           const float* __restrict__ bias,
                                           float* __restrict__ Cout,
                                           float alpha) {
    __shared__ float As[16 * 68];
    __shared__ float Ws[16 * 68];
    int n0 = blockIdx.x * 64;
    int m0 = blockIdx.y * 64;
    int tid = threadIdx.x;
    int ty = tid >> 4, tx = tid & 15;
    float acc[4][4] = {};
    for (int kk = 0; kk < 512; kk += 16) {
#pragma unroll
        for (int r = 0; r < 4; r++) {
            int l = tid + 256 * r;
            int m = l >> 4, kc = l & 15;
            As[kc * 68 + m] = A[(m0 + m) * 512 + kk + kc];
            Ws[kc * 68 + m] = W[(n0 + m) * 512 + kk + kc];
        }
        __syncthreads();
#pragma unroll
        for (int kc = 0; kc < 16; kc++) {
            float4 av = *(const float4*)&As[kc * 68 + ty * 4];
            float4 bv = *(const float4*)&Ws[kc * 68 + tx * 4];
            float a[4] = {av.x, av.y, av.z, av.w};
            float b[4] = {bv.x, bv.y, bv.z, bv.w};
#pragma unroll
            for (int i = 0; i < 4; i++)
#pragma unroll
                for (int j = 0; j < 4; j++) acc[i][j] += a[i] * b[j];
        }
        __syncthreads();
    }
#pragma unroll
    for (int i = 0; i < 4; i++) {
        int m = m0 + ty * 4 + i;
#pragma unroll
        for (int j = 0; j < 4; j++) {
            int n = n0 + tx * 4 + j;
            Cout[m * 512 + n] = alpha * (acc[i][j] + bias[n]);
        }
    }
}
// q projection: g_q = 0.125 * (qst @ Wq^T + bq)
__global__ void proj_q_kernel(const float* __restrict__ qst,
                              const float* __restrict__ ipw,
                              const float* __restrict__ ipb) {
    sgemm_body(qst, ipw, ipb, g_q, 0.125f);
}
// temp_w: g_tmp = g_ctx @ out_proj_w^T + b
__global__ void proj_tmp_kernel(const float* __restrict__ opw,
                                const float* __restrict__ opb) {
    sgemm_body(g_ctx, opw, opb, g_tmp, 1.0f);
}

// ---------------- rk[b,h,:] = q[b,h,:] @ Wk_h ; qb = q . bk_h ----------------
__global__ void rk_kernel(const float* __restrict__ in_proj_w,
                          const float* __restrict__ in_proj_b) {
    int b = blockIdx.x / Hh, h = blockIdx.x % Hh;
    __shared__ float q_s[64];
    int tid = threadIdx.x;
    if (tid < 64) q_s[tid] = g_q[b * Cc + h * 64 + tid];
    __syncthreads();
    float acc[4] = {0.f, 0.f, 0.f, 0.f};
    const float* wb = in_proj_w + (512 + h * 64) * 512;
#pragma unroll 4
    for (int d = 0; d < 64; d++) {
        float qd = q_s[d];
#pragma unroll
        for (int r = 0; r < 4; r++) acc[r] += qd * wb[d * 512 + tid + r * 128];
    }
#pragma unroll
    for (int r = 0; r < 4; r++) g_rk[(b * Hh + h) * Cc + tid + r * 128] = acc[r];
    if (tid == 0) {
        float s = 0.f;
        for (int d = 0; d < 64; d++) s += q_s[d] * in_proj_b[512 + h * 64 + d];
        g_qb[b * Hh + h] = s;
    }
}

// ---------------- attention ----------------
__global__ void attn_kernel(const float* __restrict__ data,
                            const float* __restrict__ in_proj_w,
                            const float* __restrict__ in_proj_b) {
    int b = blockIdx.x / Hh, h = blockIdx.x % Hh;
    __shared__ float rk_s[512];
    __shared__ float pr[64];
    __shared__ float pd_s[512];
    int tid = threadIdx.x;
    for (int c = tid; c < 512; c += 128) rk_s[c] = g_rk[(b * Hh + h) * Cc + c];
    __syncthreads();
    int w = tid >> 5, lane = tid & 31;
    float qb = g_qb[b * Hh + h];
    for (int ti = 0; ti < 15; ti++) {
        int t = w * 15 + ti;
        const float* dp = data + (b * Tt + t) * Cc;
        float sum = 0.f;
        for (int c = lane; c < 512; c += 32) sum += dp[c] * rk_s[c];
#pragma unroll
        for (int o = 16; o > 0; o >>= 1) sum += __shfl_down_sync(0xffffffffu, sum, o);
        if (lane == 0) pr[t] = sum + qb;
    }
    __syncthreads();
    if (tid == 0) {
        float m = pr[0];
        for (int t = 1; t < Tt; t++) m = fmaxf(m, pr[t]);
        float s = 0.f;
        for (int t = 0; t < Tt; t++) { float e = expf(pr[t] - m); pr[t] = e; s += e; }
        float inv = 1.0f / s;
        for (int t = 0; t < Tt; t++) pr[t] *= inv;
    }
    __syncthreads();
    for (int c = tid; c < 512; c += 128) {
        float a = 0.f;
        const float* dp = data + b * Tt * Cc + c;
#pragma unroll 4
        for (int t = 0; t < Tt; t++) a += pr[t] * dp[t * Cc];
        pd_s[c] = a;
    }
    __syncthreads();
    for (int di = 0; di < 16; di++) {
        int d = w * 16 + di;
        const float* wr = in_proj_w + (1024 + h * 64 + d) * 512;
        float sum = 0.f;
        for (int c = lane; c < 512; c += 32) sum += wr[c] * pd_s[c];
#pragma unroll
        for (int o = 16; o > 0; o >>= 1) sum += __shfl_down_sync(0xffffffffu, sum, o);
        if (lane == 0) g_ctx[b * Cc + h * 64 + d] = sum + in_proj_b[1024 + h * 64 + d];
    }
}

// ---------------- router + top-k + beta time weights ----------------
__global__ void router_kernel(const float* __restrict__ router_w,
                              const float* __restrict__ router_b,
                              const float* __restrict__ beta_w,
                              const float* __restrict__ beta_b) {
    int b = blockIdx.x;
    __shared__ float tmp_s[512];
    __shared__ float logit[32];
    __shared__ float al[Ee], be[Ee];
    __shared__ int sel_i[Kk];
    __shared__ float w_s[Kk * Tt];
    int tid = threadIdx.x;
    for (int c = tid; c < 512; c += 256) tmp_s[c] = g_tmp[b * Cc + c];
    __syncthreads();
    int w = tid >> 5, lane = tid & 31;
    for (int r = w; r < 30; r += 8) {
        const float* wr; float bias;
        if (r < Ee) { wr = router_w + r * 512; bias = router_b[r]; }
        else { wr = beta_w + (r - Ee) * 512; bias = beta_b[r - Ee]; }
        float s = 0.f;
        for (int c = lane; c < 512; c += 32) s += wr[c] * tmp_s[c];
#pragma unroll
        for (int o = 16; o > 0; o >>= 1) s += __shfl_down_sync(0xffffffffu, s, o);
        if (lane == 0) logit[r] = s + bias;
    }
    __syncthreads();
    if (tid < Ee) {
        al[tid] = softplus_f(logit[Ee + 2 * tid]) + 1e-6f;
        be[tid] = softplus_f(logit[Ee + 2 * tid + 1]) + 1e-6f;
    }
    if (tid == 0) {
        float m = logit[0];
        for (int e = 1; e < Ee; e++) m = fmaxf(m, logit[e]);
        float pe[Ee]; float s = 0.f;
        for (int e = 0; e < Ee; e++) { pe[e] = expf(logit[e] - m); s += pe[e]; }
        float invs = 1.0f / s;
        for (int e = 0; e < Ee; e++) pe[e] *= invs;
        bool used[Ee] = {};
        float psum = 0.f; float sp[Kk];
        for (int kk = 0; kk < Kk; kk++) {
            int best = 0; float bv = -1.f;
            for (int e = 0; e < Ee; e++)
                if (!used[e] && pe[e] > bv) { bv = pe[e]; best = e; }
            used[best] = true; sel_i[kk] = best; sp[kk] = bv; psum += bv;
        }
        float inv = 1.0f / (psum + 1e-8f);
        for (int kk = 0; kk < Kk; kk++) {
            g_topk_i[b * Kk + kk] = sel_i[kk];
            g_topk_p[b * Kk + kk] = sp[kk] * inv;
        }
    }
    __syncthreads();
    for (int i = tid; i < Kk * Tt; i += 256) {
        int kk = i / Tt, t = i % Tt;
        int e = sel_i[kk];
        float a = al[e], bb = be[e];
        float tt = (float)t / 59.0f;
        float lt = logf(tt + 1e-12f);
        float l1 = logf(1.0f - tt + 1e-12f);
        float norm = lgammaf(a) + lgammaf(bb) - lgammaf(a + bb);
        w_s[i] = expf((a - 1.0f) * lt + (bb - 1.0f) * l1 - norm);
    }
    __syncthreads();
    if (tid < Kk) {
        float m = 0.f;
        for (int t = 0; t < Tt; t++) m = fmaxf(m, w_s[tid * Tt + t]);
        float inv = 1.0f / (m + 1e-8f);
        float s = 0.f;
        for (int t = 0; t < Tt; t++) {
            float v = w_s[tid * Tt + t] * inv;
            g_tw[(b * Kk + tid) * Tt + t] = v;
            s += v;
        }
        g_sw[b * Kk + tid] = s;
    }
}

// ---------------- layer1 via tensor cores (bf16 3-term split, K'=1536) ----------------
// grid (4, B*K), 256 threads (8 warps). Block tile 64x64, warp = (mw 0..3, nw 0..1).
// K' segments: seg0 = A_hi*W_hi, seg1 = A_lo*W_hi, seg2 = A_hi*W_lo.
__global__ void layer1_mma_kernel(const float* __restrict__ b1) {
    __shared__ __nv_bfloat16 As[64 * 72];  // 144B pitch: conflict-free
    __shared__ __nv_bfloat16 Bs[64 * 72];
    __shared__ float tw_s[64];
    __shared__ float red[4 * 68];
    int bk = blockIdx.y;
    int b = bk / Kk;
    int n0blk = blockIdx.x * 64;
    int e = g_topk_i[bk];
    int tid = threadIdx.x;
    int warp = tid >> 5, lane = tid & 31;
    int mw = warp >> 1, nw = warp & 1;

    if (tid < 64) tw_s[tid] = (tid < Tt) ? g_tw[bk * Tt + tid] : 0.0f;

    long aoff = (long)b * (Tt * Cc);
    long boff = (long)e * (256 * Cc) + (long)n0blk * Cc;
    const __nv_bfloat16* Aseg[3];
    const __nv_bfloat16* Bseg[3];
    Aseg[0] = g_dhi + aoff;  Bseg[0] = g_w1hi + boff;
    Aseg[1] = g_dlo + aoff;  Bseg[1] = g_w1hi + boff;
    Aseg[2] = g_dhi + aoff;  Bseg[2] = g_w1lo + boff;

    float acc[4][4] = {};  // 4 n-tiles x 4 regs
    for (int ch = 0; ch < 24; ch++) {
        int seg = ch >> 3;
        int kb = (ch & 7) * 64;
        const __nv_bfloat16* Ap = Aseg[seg];
        const __nv_bfloat16* Bp = Bseg[seg];
        uint4 av[2], bv[2];
#pragma unroll
        for (int r = 0; r < 2; r++) {
            int idx = r * 256 + tid;
            int row = idx >> 3;
            int c = (idx & 7) * 8;
            av[r] = (row < Tt) ? *(const uint4*)(Ap + row * Cc + kb + c)
                               : make_uint4(0u, 0u, 0u, 0u);
            bv[r] = *(const uint4*)(Bp + row * Cc + kb + c);
        }
        __syncthreads();
#pragma unroll
        for (int r = 0; r < 2; r++) {
            int idx = r * 256 + tid;
            int row = idx >> 3;
            int c = (idx & 7) * 8;
            *(uint4*)(As + row * 72 + c) = av[r];
            *(uint4*)(Bs + row * 72 + c) = bv[r];
        }
        __syncthreads();
#pragma unroll
        for (int ks = 0; ks < 4; ks++) {
            uint32_t a[4];
            int arow = mw * 16 + (lane & 15);
            int acol = ks * 16 + (lane >> 4) * 8;
            ldm_x4(a, smem_u32(As + arow * 72 + acol));
            uint32_t bf[8];
#pragma unroll
            for (int half = 0; half < 2; half++) {
                int nbase = nw * 32 + half * 16;
                int grp = lane >> 3, l8 = lane & 7;
                int nrow = nbase + (grp >> 1) * 8 + l8;
                int kcol = ks * 16 + (grp & 1) * 8;
                ldm_x4(bf + half * 4, smem_u32(Bs + nrow * 72 + kcol));
            }
#pragma unroll
            for (int j = 0; j < 4; j++) mma16816(acc[j], a, bf + j * 2);
        }
    }
    // epilogue: relu(c + b1) * tw[t], reduce over t
    int g = lane >> 2, t4 = lane & 3;
    int r0 = mw * 16 + g, r1 = r0 + 8;
    float w0 = tw_s[r0], w1 = tw_s[r1];
#pragma unroll
    for (int j = 0; j < 4; j++) {
        int nc0 = nw * 32 + j * 8 + t4 * 2;
        float bias0 = b1[e * 256 + n0blk + nc0];
        float bias1 = b1[e * 256 + n0blk + nc0 + 1];
        float s0 = w0 * fmaxf(acc[j][0] + bias0, 0.f) + w1 * fmaxf(acc[j][2] + bias0, 0.f);
        float s1 = w0 * fmaxf(acc[j][1] + bias1, 0.f) + w1 * fmaxf(acc[j][3] + bias1, 0.f);
#pragma unroll
        for (int o = 16; o >= 4; o >>= 1) {
            s0 += __shfl_down_sync(0xffffffffu, s0, o);
            s1 += __shfl_down_sync(0xffffffffu, s1, o);
        }
        if (g == 0) {
            red[mw * 68 + nc0] = s0;
            red[mw * 68 + nc0 + 1] = s1;
        }
    }
    __syncthreads();
    if (tid < 64) {
        float p = red[tid] + red[68 + tid] + red[136 + tid] + red[204 + tid];
        g_pooled[bk * 256 + n0blk + tid] = p;
    }
}

// ---------------- layer2 + router combine + LayerNorm (per b) ----------------
__global__ void final_kernel(const float* __restrict__ b2,
                             const float* __restrict__ ln_g,
                             const float* __restrict__ ln_b,
                             float* __restrict__ out) {
    int b = blockIdx.x;
    int tid = threadIdx.x;
    __shared__ float sp[256];
    __shared__ float red[18];
    float y0 = 0.f, y1 = 0.f;
    int c0 = tid, c1 = tid + 256;
    for (int kk = 0; kk < Kk; kk++) {
        int e = g_topk_i[b * Kk + kk];
        float p = g_topk_p[b * Kk + kk];
        float sw = g_sw[b * Kk + kk];
        __syncthreads();
        sp[tid] = g_pooled[(b * Kk + kk) * 256 + tid];
        __syncthreads();
        float a0 = 0.f, a1 = 0.f;
        const float* wt = g_w2t + e * 256 * Cc;
#pragma unroll 4
        for (int j = 0; j < 256; j++) {
            float sv = sp[j];
            a0 += sv * wt[j * Cc + c0];
            a1 += sv * wt[j * Cc + c1];
        }
        y0 += p * (a0 + sw * b2[e * Cc + c0]);
        y1 += p * (a1 + sw * b2[e * Cc + c1]);
    }
    float s = y0 + y1, sq = y0 * y0 + y1 * y1;
    int w = tid >> 5, lane = tid & 31;
#pragma unroll
    for (int o = 16; o > 0; o >>= 1) {
        s += __shfl_down_sync(0xffffffffu, s, o);
        sq += __shfl_down_sync(0xffffffffu, sq, o);
    }
    if (lane == 0) { red[w] = s; red[8 + w] = sq; }
    __syncthreads();
    if (tid == 0) {
        float S = 0.f, SQ = 0.f;
        for (int i = 0; i < 8; i++) { S += red[i]; SQ += red[8 + i]; }
        red[16] = S; red[17] = SQ;
    }
    __syncthreads();
    float mean = red[16] * (1.0f / 512.0f);
    float var = red[17] * (1.0f / 512.0f) - mean * mean;
    float rstd = rsqrtf(var + 1e-5f);
    out[b * Cc + c0] = (y0 - mean) * rstd * ln_g[c0] + ln_b[c0];
    out[b * Cc + c1] = (y1 - mean) * rstd * ln_g[c1] + ln_b[c1];
}

// ---------------- launch ----------------
extern "C" void kernel_launch(void* const* d_in, const int* in_sizes, int n_in,
                              void* d_out, int out_size) {
    const float* qst = (const float*)d_in[0];
    const float* data = (const float*)d_in[1];
    const float* ipw = (const float*)d_in[2];
    const float* ipb = (const float*)d_in[3];
    const float* opw = (const float*)d_in[4];
    const float* opb = (const float*)d_in[5];
    const float* rw  = (const float*)d_in[6];
    const float* rb  = (const float*)d_in[7];
    const float* bw  = (const float*)d_in[8];
    const float* bb  = (const float*)d_in[9];
    const float* w1  = (const float*)d_in[10];
    const float* b1  = (const float*)d_in[11];
    const float* w2  = (const float*)d_in[12];
    const float* b2  = (const float*)d_in[13];
    const float* lng = (const float*)d_in[14];
    const float* lnb = (const float*)d_in[15];
    float* out = (float*)d_out;

    split_data_kernel<<<(Bb * Tt * Cc + 255) / 256, 256>>>(data);
    split_w1_kernel<<<(Ee * 256 * Cc + 255) / 256, 256>>>(w1);
    transpose_w2_kernel<<<dim3(8, 16, 10), dim3(32, 8)>>>(w2);
    proj_q_kernel<<<dim3(8, 4), 256>>>(qst, ipw, ipb);
    rk_kernel<<<Bb * Hh, 128>>>(ipw, ipb);
    attn_kernel<<<Bb * Hh, 128>>>(data, ipw, ipb);
    proj_tmp_kernel<<<dim3(8, 4), 256>>>(opw, opb);
    router_kernel<<<Bb, 256>>>(rw, rb, bw, bb);
    layer1_mma_kernel<<<dim3(4, Bb * Kk), 256>>>(b1);
    final_kernel<<<Bb, 256>>>(b2, lng, lnb, out);
}

// round 5
// speedup vs baseline: 1.5228x; 1.1184x over previous
#include <cuda_runtime.h>
#include <cuda_bf16.h>
#include <cstdint>
#include <math.h>

#define Bb 256
#define Tt 60
#define Cc 512
#define Ee 10
#define Kk 5
#define Hh 8
#define DH 64

// ---------------- scratch (device globals; no allocation allowed) ----------------
__device__ float g_q[Bb * Cc];
__device__ float g_rk[Bb * Hh * Cc];
__device__ float g_qb[Bb * Hh];
__device__ float g_ctx[Bb * Cc];
__device__ float g_tmp[Bb * Cc];
__device__ int   g_topk_i[Bb * Kk];
__device__ float g_topk_p[Bb * Kk];
__device__ float g_tw[Bb * Kk * Tt];
__device__ float g_sw[Bb * Kk];
__device__ float g_pooled[Bb * Kk * 256];
__device__ float g_w2t[Ee * 256 * Cc];
__device__ __nv_bfloat16 g_dhi[Bb * Tt * Cc];
__device__ __nv_bfloat16 g_dlo[Bb * Tt * Cc];
__device__ __nv_bfloat16 g_w1hi[Ee * 256 * Cc];
__device__ __nv_bfloat16 g_w1lo[Ee * 256 * Cc];

// ---------------- helpers ----------------
__device__ __forceinline__ float softplus_f(float x) {
    return fmaxf(x, 0.0f) + log1pf(expf(-fabsf(x)));
}
__device__ __forceinline__ uint32_t smem_u32(const void* p) {
    return (uint32_t)__cvta_generic_to_shared(p);
}
__device__ __forceinline__ void ldm_x4(uint32_t* r, uint32_t addr) {
    asm volatile("ldmatrix.sync.aligned.m8n8.x4.shared.b16 {%0,%1,%2,%3}, [%4];"
                 : "=r"(r[0]), "=r"(r[1]), "=r"(r[2]), "=r"(r[3]) : "r"(addr));
}
__device__ __forceinline__ void mma16816(float* c, const uint32_t* a, const uint32_t* b) {
    asm volatile(
        "mma.sync.aligned.m16n8k16.row.col.f32.bf16.bf16.f32 "
        "{%0,%1,%2,%3}, {%4,%5,%6,%7}, {%8,%9}, {%0,%1,%2,%3};"
        : "+f"(c[0]), "+f"(c[1]), "+f"(c[2]), "+f"(c[3])
        : "r"(a[0]), "r"(a[1]), "r"(a[2]), "r"(a[3]), "r"(b[0]), "r"(b[1]));
}
__device__ __forceinline__ void cp16(uint32_t dst, const void* src, int srcsize) {
    asm volatile("cp.async.cg.shared.global [%0], [%1], 16, %2;\n"
                 :: "r"(dst), "l"(src), "r"(srcsize));
}
__device__ __forceinline__ void cp_commit() {
    asm volatile("cp.async.commit_group;\n");
}
template <int N>
__device__ __forceinline__ void cp_wait() {
    asm volatile("cp.async.wait_group %0;\n" :: "n"(N));
}

// ---------------- fp32 -> (bf16 hi, bf16 lo) splits ----------------
__global__ void split_data_kernel(const float* __restrict__ x) {
    int i = blockIdx.x * 256 + threadIdx.x;
    if (i < Bb * Tt * Cc) {
        float v = x[i];
        __nv_bfloat16 h = __float2bfloat16(v);
        g_dhi[i] = h;
        g_dlo[i] = __float2bfloat16(v - __bfloat162float(h));
    }
}
__global__ void split_w1_kernel(const float* __restrict__ x) {
    int i = blockIdx.x * 256 + threadIdx.x;
    if (i < Ee * 256 * Cc) {
        float v = x[i];
        __nv_bfloat16 h = __float2bfloat16(v);
        g_w1hi[i] = h;
        g_w1lo[i] = __float2bfloat16(v - __bfloat162float(h));
    }
}

// ---------------- W2 transpose: [E][C][256] -> [E][256][C] ----------------
__global__ void transpose_w2_kernel(const float* __restrict__ w2) {
    __shared__ float t[32][33];
    int e = blockIdx.z;
    int j0 = blockIdx.x * 32;
    int c0 = blockIdx.y * 32;
    int tx = threadIdx.x, ty = threadIdx.y;
#pragma unroll
    for (int r = 0; r < 4; r++) {
        int c = c0 + ty + r * 8;
        t[ty + r * 8][tx] = w2[(e * Cc + c) * 256 + j0 + tx];
    }
    __syncthreads();
#pragma unroll
    for (int r = 0; r < 4; r++) {
        int j = j0 + ty + r * 8;
        g_w2t[(e * 256 + j) * Cc + c0 + tx] = t[tx][ty + r * 8];
    }
}

// ---------------- small SGEMM, 32x64 tiles (better occupancy for tiny GEMMs) ----------------
__device__ __forceinline__ void sgemm_body32(const float* __restrict__ A,
                                             const float* __restrict__ W,
                                             const float* __restrict__ bias,
                                             float* __restrict__ Cout,
                                             float alpha) {
    __shared__ float As[16 * 36];
    __shared__ float Ws[16 * 68];
    int n0 = blockIdx.x * 64;
    int m0 = blockIdx.y * 32;
    int tid = threadIdx.x;
    int ty = tid >> 4, tx = tid & 15;
    float acc[2][4] = {};
    for (int kk = 0; kk < 512; kk += 16) {
#pragma unroll
        for (int r = 0; r < 2; r++) {
            int l = r * 256 + tid;
            int m = l >> 4, kc = l & 15;
            As[kc * 36 + m] = A[(m0 + m) * 512 + kk + kc];
        }
#pragma unroll
        for (int r = 0; r < 4; r++) {
            int l = r * 256 + tid;
            int n = l >> 4, kc = l & 15;
            Ws[kc * 68 + n] = W[(n0 + n) * 512 + kk + kc];
        }
        __syncthreads();
#pragma unroll
        for (int kc = 0; kc < 16; kc++) {
            float a0 = As[kc * 36 + ty * 2];
            float a1 = As[kc * 36 + ty * 2 + 1];
            float4 bv = *(const float4*)&Ws[kc * 68 + tx * 4];
            acc[0][0] += a0 * bv.x; acc[0][1] += a0 * bv.y;
            acc[0][2] += a0 * bv.z; acc[0][3] += a0 * bv.w;
            acc[1][0] += a1 * bv.x; acc[1][1] += a1 * bv.y;
            acc[1][2] += a1 * bv.z; acc[1][3] += a1 * bv.w;
        }
        __syncthreads();
    }
#pragma unroll
    for (int i = 0; i < 2; i++) {
        int m = m0 + ty * 2 + i;
#pragma unroll
        for (int j = 0; j < 4; j++) {
            int n = n0 + tx * 4 + j;
            Cout[m * 512 + n] = alpha * (acc[i][j] + bias[n]);
        }
    }
}
__global__ void proj_q_kernel(const float* __restrict__ qst,
                              const float* __restrict__ ipw,
                              const float* __restrict__ ipb) {
    sgemm_body32(qst, ipw, ipb, g_q, 0.125f);
}
__global__ void proj_tmp_kernel(const float* __restrict__ opw,
                                const float* __restrict__ opb) {
    sgemm_body32(g_ctx, opw, opb, g_tmp, 1.0f);
}

// ---------------- rk[b,h,:] = q[b,h,:] @ Wk_h ; qb = q . bk_h ----------------
__global__ void rk_kernel(const float* __restrict__ in_proj_w,
                          const float* __restrict__ in_proj_b) {
    int b = blockIdx.x / Hh, h = blockIdx.x % Hh;
    __shared__ float q_s[64];
    int tid = threadIdx.x;
    if (tid < 64) q_s[tid] = g_q[b * Cc + h * 64 + tid];
    __syncthreads();
    float acc[4] = {0.f, 0.f, 0.f, 0.f};
    const float* wb = in_proj_w + (512 + h * 64) * 512;
#pragma unroll 4
    for (int d = 0; d < 64; d++) {
        float qd = q_s[d];
#pragma unroll
        for (int r = 0; r < 4; r++) acc[r] += qd * wb[d * 512 + tid + r * 128];
    }
#pragma unroll
    for (int r = 0; r < 4; r++) g_rk[(b * Hh + h) * Cc + tid + r * 128] = acc[r];
    if (tid == 0) {
        float s = 0.f;
        for (int d = 0; d < 64; d++) s += q_s[d] * in_proj_b[512 + h * 64 + d];
        g_qb[b * Hh + h] = s;
    }
}

// ---------------- attention ----------------
__global__ void attn_kernel(const float* __restrict__ data,
                            const float* __restrict__ in_proj_w,
                            const float* __restrict__ in_proj_b) {
    int b = blockIdx.x / Hh, h = blockIdx.x % Hh;
    __shared__ float rk_s[512];
    __shared__ float pr[64];
    __shared__ float pd_s[512];
    int tid = threadIdx.x;
    for (int c = tid; c < 512; c += 128) rk_s[c] = g_rk[(b * Hh + h) * Cc + c];
    __syncthreads();
    int w = tid >> 5, lane = tid & 31;
    float qb = g_qb[b * Hh + h];
    for (int ti = 0; ti < 15; ti++) {
        int t = w * 15 + ti;
        const float* dp = data + (b * Tt + t) * Cc;
        float sum = 0.f;
        for (int c = lane; c < 512; c += 32) sum += dp[c] * rk_s[c];
#pragma unroll
        for (int o = 16; o > 0; o >>= 1) sum += __shfl_down_sync(0xffffffffu, sum, o);
        if (lane == 0) pr[t] = sum + qb;
    }
    __syncthreads();
    if (tid == 0) {
        float m = pr[0];
        for (int t = 1; t < Tt; t++) m = fmaxf(m, pr[t]);
        float s = 0.f;
        for (int t = 0; t < Tt; t++) { float e = expf(pr[t] - m); pr[t] = e; s += e; }
        float inv = 1.0f / s;
        for (int t = 0; t < Tt; t++) pr[t] *= inv;
    }
    __syncthreads();
    for (int c = tid; c < 512; c += 128) {
        float a = 0.f;
        const float* dp = data + b * Tt * Cc + c;
#pragma unroll 4
        for (int t = 0; t < Tt; t++) a += pr[t] * dp[t * Cc];
        pd_s[c] = a;
    }
    __syncthreads();
    for (int di = 0; di < 16; di++) {
        int d = w * 16 + di;
        const float* wr = in_proj_w + (1024 + h * 64 + d) * 512;
        float sum = 0.f;
        for (int c = lane; c < 512; c += 32) sum += wr[c] * pd_s[c];
#pragma unroll
        for (int o = 16; o > 0; o >>= 1) sum += __shfl_down_sync(0xffffffffu, sum, o);
        if (lane == 0) g_ctx[b * Cc + h * 64 + d] = sum + in_proj_b[1024 + h * 64 + d];
    }
}

// ---------------- router + top-k + beta time weights ----------------
__global__ void router_kernel(const float* __restrict__ router_w,
                              const float* __restrict__ router_b,
                              const float* __restrict__ beta_w,
                              const float* __restrict__ beta_b) {
    int b = blockIdx.x;
    __shared__ float tmp_s[512];
    __shared__ float logit[32];
    __shared__ float al[Ee], be[Ee];
    __shared__ int sel_i[Kk];
    __shared__ float w_s[Kk * Tt];
    int tid = threadIdx.x;
    for (int c = tid; c < 512; c += 256) tmp_s[c] = g_tmp[b * Cc + c];
    __syncthreads();
    int w = tid >> 5, lane = tid & 31;
    for (int r = w; r < 30; r += 8) {
        const float* wr; float bias;
        if (r < Ee) { wr = router_w + r * 512; bias = router_b[r]; }
        else { wr = beta_w + (r - Ee) * 512; bias = beta_b[r - Ee]; }
        float s = 0.f;
        for (int c = lane; c < 512; c += 32) s += wr[c] * tmp_s[c];
#pragma unroll
        for (int o = 16; o > 0; o >>= 1) s += __shfl_down_sync(0xffffffffu, s, o);
        if (lane == 0) logit[r] = s + bias;
    }
    __syncthreads();
    if (tid < Ee) {
        al[tid] = softplus_f(logit[Ee + 2 * tid]) + 1e-6f;
        be[tid] = softplus_f(logit[Ee + 2 * tid + 1]) + 1e-6f;
    }
    if (tid == 0) {
        float m = logit[0];
        for (int e = 1; e < Ee; e++) m = fmaxf(m, logit[e]);
        float pe[Ee]; float s = 0.f;
        for (int e = 0; e < Ee; e++) { pe[e] = expf(logit[e] - m); s += pe[e]; }
        float invs = 1.0f / s;
        for (int e = 0; e < Ee; e++) pe[e] *= invs;
        bool used[Ee] = {};
        float psum = 0.f; float sp[Kk];
        for (int kk = 0; kk < Kk; kk++) {
            int best = 0; float bv = -1.f;
            for (int e = 0; e < Ee; e++)
                if (!used[e] && pe[e] > bv) { bv = pe[e]; best = e; }
            used[best] = true; sel_i[kk] = best; sp[kk] = bv; psum += bv;
        }
        float inv = 1.0f / (psum + 1e-8f);
        for (int kk = 0; kk < Kk; kk++) {
            g_topk_i[b * Kk + kk] = sel_i[kk];
            g_topk_p[b * Kk + kk] = sp[kk] * inv;
        }
    }
    __syncthreads();
    for (int i = tid; i < Kk * Tt; i += 256) {
        int kk = i / Tt, t = i % Tt;
        int e = sel_i[kk];
        float a = al[e], bb = be[e];
        float tt = (float)t / 59.0f;
        float lt = logf(tt + 1e-12f);
        float l1 = logf(1.0f - tt + 1e-12f);
        float norm = lgammaf(a) + lgammaf(bb) - lgammaf(a + bb);
        w_s[i] = expf((a - 1.0f) * lt + (bb - 1.0f) * l1 - norm);
    }
    __syncthreads();
    if (tid < Kk) {
        float m = 0.f;
        for (int t = 0; t < Tt; t++) m = fmaxf(m, w_s[tid * Tt + t]);
        float inv = 1.0f / (m + 1e-8f);
        float s = 0.f;
        for (int t = 0; t < Tt; t++) {
            float v = w_s[tid * Tt + t] * inv;
            g_tw[(b * Kk + tid) * Tt + t] = v;
            s += v;
        }
        g_sw[b * Kk + tid] = s;
    }
}

// ---------------- layer1 via tensor cores, cp.async double-buffered ----------------
// grid (4, B*K), 256 threads (8 warps). Block tile 64x64, warp = (mw 0..3, nw 0..1).
// K' segments: seg0 = A_hi*W_hi, seg1 = A_lo*W_hi, seg2 = A_hi*W_lo. 24 chunks of k=64.
__global__ void layer1_mma_kernel(const float* __restrict__ b1) {
    __shared__ __nv_bfloat16 As[2][64 * 72];
    __shared__ __nv_bfloat16 Bs[2][64 * 72];
    __shared__ float tw_s[64];
    __shared__ float red[4 * 68];
    int bk = blockIdx.y;
    int b = bk / Kk;
    int n0blk = blockIdx.x * 64;
    int e = g_topk_i[bk];
    int tid = threadIdx.x;
    int warp = tid >> 5, lane = tid & 31;
    int mw = warp >> 1, nw = warp & 1;

    if (tid < 64) tw_s[tid] = (tid < Tt) ? g_tw[bk * Tt + tid] : 0.0f;

    long aoff = (long)b * (Tt * Cc);
    long boff = (long)e * (256 * Cc) + (long)n0blk * Cc;
    const __nv_bfloat16* Aseg[3];
    const __nv_bfloat16* Bseg[3];
    Aseg[0] = g_dhi + aoff;  Bseg[0] = g_w1hi + boff;
    Aseg[1] = g_dlo + aoff;  Bseg[1] = g_w1hi + boff;
    Aseg[2] = g_dhi + aoff;  Bseg[2] = g_w1lo + boff;

    // per-thread copy mapping: idx = r*256+tid; row = idx>>3; c = (idx&7)*8 (16B)
    int row0 = tid >> 3, c0 = (tid & 7) * 8;
    int row1 = (256 + tid) >> 3, c1 = c0;

    auto issue = [&](int ch, int buf) {
        int seg = ch >> 3;
        int kb = (ch & 7) * 64;
        const __nv_bfloat16* Ap = Aseg[seg];
        const __nv_bfloat16* Bp = Bseg[seg];
        const __nv_bfloat16* a0 = (row0 < Tt) ? (Ap + row0 * Cc + kb + c0) : Ap;
        const __nv_bfloat16* a1 = (row1 < Tt) ? (Ap + row1 * Cc + kb + c1) : Ap;
        cp16(smem_u32(&As[buf][row0 * 72 + c0]), a0, row0 < Tt ? 16 : 0);
        cp16(smem_u32(&Bs[buf][row0 * 72 + c0]), Bp + row0 * Cc + kb + c0, 16);
        cp16(smem_u32(&As[buf][row1 * 72 + c1]), a1, row1 < Tt ? 16 : 0);
        cp16(smem_u32(&Bs[buf][row1 * 72 + c1]), Bp + row1 * Cc + kb + c1, 16);
        cp_commit();
    };

    float acc[4][4] = {};
    issue(0, 0);
    for (int ch = 0; ch < 24; ch++) {
        int cur = ch & 1;
        if (ch < 23) { issue(ch + 1, cur ^ 1); cp_wait<1>(); }
        else { cp_wait<0>(); }
        __syncthreads();
#pragma unroll
        for (int ks = 0; ks < 4; ks++) {
            uint32_t a[4];
            int arow = mw * 16 + (lane & 15);
            int acol = ks * 16 + (lane >> 4) * 8;
            ldm_x4(a, smem_u32(&As[cur][arow * 72 + acol]));
            uint32_t bf[8];
#pragma unroll
            for (int half = 0; half < 2; half++) {
                int nbase = nw * 32 + half * 16;
                int grp = lane >> 3, l8 = lane & 7;
                int nrow = nbase + (grp >> 1) * 8 + l8;
                int kcol = ks * 16 + (grp & 1) * 8;
                ldm_x4(bf + half * 4, smem_u32(&Bs[cur][nrow * 72 + kcol]));
            }
#pragma unroll
            for (int j = 0; j < 4; j++) mma16816(acc[j], a, bf + j * 2);
        }
        __syncthreads();
    }
    // epilogue: relu(c + b1) * tw[t], reduce over t
    int g = lane >> 2, t4 = lane & 3;
    int r0 = mw * 16 + g, r1 = r0 + 8;
    float w0 = tw_s[r0], w1 = tw_s[r1];
#pragma unroll
    for (int j = 0; j < 4; j++) {
        int nc0 = nw * 32 + j * 8 + t4 * 2;
        float bias0 = b1[e * 256 + n0blk + nc0];
        float bias1 = b1[e * 256 + n0blk + nc0 + 1];
        float s0 = w0 * fmaxf(acc[j][0] + bias0, 0.f) + w1 * fmaxf(acc[j][2] + bias0, 0.f);
        float s1 = w0 * fmaxf(acc[j][1] + bias1, 0.f) + w1 * fmaxf(acc[j][3] + bias1, 0.f);
#pragma unroll
        for (int o = 16; o >= 4; o >>= 1) {
            s0 += __shfl_down_sync(0xffffffffu, s0, o);
            s1 += __shfl_down_sync(0xffffffffu, s1, o);
        }
        if (g == 0) {
            red[mw * 68 + nc0] = s0;
            red[mw * 68 + nc0 + 1] = s1;
        }
    }
    __syncthreads();
    if (tid < 64) {
        float p = red[tid] + red[68 + tid] + red[136 + tid] + red[204 + tid];
        g_pooled[bk * 256 + n0blk + tid] = p;
    }
}

// ---------------- layer2 + router combine + LayerNorm (per b) ----------------
__global__ void final_kernel(const float* __restrict__ b2,
                             const float* __restrict__ ln_g,
                             const float* __restrict__ ln_b,
                             float* __restrict__ out) {
    int b = blockIdx.x;
    int tid = threadIdx.x;
    __shared__ float sp[256];
    __shared__ float red[18];
    float y0 = 0.f, y1 = 0.f;
    int c0 = tid, c1 = tid + 256;
    for (int kk = 0; kk < Kk; kk++) {
        int e = g_topk_i[b * Kk + kk];
        float p = g_topk_p[b * Kk + kk];
        float sw = g_sw[b * Kk + kk];
        __syncthreads();
        sp[tid] = g_pooled[(b * Kk + kk) * 256 + tid];
        __syncthreads();
        float a0 = 0.f, a1 = 0.f;
        const float* wt = g_w2t + e * 256 * Cc;
#pragma unroll 4
        for (int j = 0; j < 256; j++) {
            float sv = sp[j];
            a0 += sv * wt[j * Cc + c0];
            a1 += sv * wt[j * Cc + c1];
        }
        y0 += p * (a0 + sw * b2[e * Cc + c0]);
        y1 += p * (a1 + sw * b2[e * Cc + c1]);
    }
    float s = y0 + y1, sq = y0 * y0 + y1 * y1;
    int w = tid >> 5, lane = tid & 31;
#pragma unroll
    for (int o = 16; o > 0; o >>= 1) {
        s += __shfl_down_sync(0xffffffffu, s, o);
        sq += __shfl_down_sync(0xffffffffu, sq, o);
    }
    if (lane == 0) { red[w] = s; red[8 + w] = sq; }
    __syncthreads();
    if (tid == 0) {
        float S = 0.f, SQ = 0.f;
        for (int i = 0; i < 8; i++) { S += red[i]; SQ += red[8 + i]; }
        red[16] = S; red[17] = SQ;
    }
    __syncthreads();
    float mean = red[16] * (1.0f / 512.0f);
    float var = red[17] * (1.0f / 512.0f) - mean * mean;
    float rstd = rsqrtf(var + 1e-5f);
    out[b * Cc + c0] = (y0 - mean) * rstd * ln_g[c0] + ln_b[c0];
    out[b * Cc + c1] = (y1 - mean) * rstd * ln_g[c1] + ln_b[c1];
}

// ---------------- launch ----------------
extern "C" void kernel_launch(void* const* d_in, const int* in_sizes, int n_in,
                              void* d_out, int out_size) {
    const float* qst = (const float*)d_in[0];
    const float* data = (const float*)d_in[1];
    const float* ipw = (const float*)d_in[2];
    const float* ipb = (const float*)d_in[3];
    const float* opw = (const float*)d_in[4];
    const float* opb = (const float*)d_in[5];
    const float* rw  = (const float*)d_in[6];
    const float* rb  = (const float*)d_in[7];
    const float* bw  = (const float*)d_in[8];
    const float* bb  = (const float*)d_in[9];
    const float* w1  = (const float*)d_in[10];
    const float* b1  = (const float*)d_in[11];
    const float* w2  = (const float*)d_in[12];
    const float* b2  = (const float*)d_in[13];
    const float* lng = (const float*)d_in[14];
    const float* lnb = (const float*)d_in[15];
    float* out = (float*)d_out;

    split_data_kernel<<<(Bb * Tt * Cc + 255) / 256, 256>>>(data);
    split_w1_kernel<<<(Ee * 256 * Cc + 255) / 256, 256>>>(w1);
    transpose_w2_kernel<<<dim3(8, 16, 10), dim3(32, 8)>>>(w2);
    proj_q_kernel<<<dim3(8, 8), 256>>>(qst, ipw, ipb);
    rk_kernel<<<Bb * Hh, 128>>>(ipw, ipb);
    attn_kernel<<<Bb * Hh, 128>>>(data, ipw, ipb);
    proj_tmp_kernel<<<dim3(8, 8), 256>>>(opw, opb);
    router_kernel<<<Bb, 256>>>(rw, rb, bw, bb);
    layer1_mma_kernel<<<dim3(4, Bb * Kk), 256>>>(b1);
    final_kernel<<<Bb, 256>>>(b2, lng, lnb, out);
}

// round 6
// speedup vs baseline: 1.9035x; 1.2500x over previous
#include <cuda_runtime.h>
#include <cuda_bf16.h>
#include <cstdint>
#include <math.h>

#define Bb 256
#define Tt 60
#define Cc 512
#define Ee 10
#define Kk 5
#define Hh 8
#define DH 64

// ---------------- scratch (device globals) ----------------
__device__ float g_q[Bb * Cc];
__device__ float g_rk[Bb * Hh * Cc];      // (b*8+h)*512 + c
__device__ float g_ctx[Bb * Cc];
__device__ float g_tmp[Bb * Cc];
__device__ int   g_topk_i[Bb * Kk];
__device__ float g_topk_p[Bb * Kk];
__device__ float g_tw[Bb * Kk * Tt];
__device__ float g_sw[Bb * Kk];
__device__ float g_pooled[Bb * Kk * 256];
__device__ float g_pd[Bb * Hh * Cc];      // pooled data per head
__device__ float g_perexp[Bb * Kk * Cc];  // layer2 per-pair output (+ sw*b2)
__device__ int   g_glist[Ee * 256];
__device__ int   g_cnt[Ee];
__device__ __nv_bfloat16 g_dhi[Bb * Tt * Cc];
__device__ __nv_bfloat16 g_dlo[Bb * Tt * Cc];
__device__ __nv_bfloat16 g_w1hi[Ee * 256 * Cc];
__device__ __nv_bfloat16 g_w1lo[Ee * 256 * Cc];

// ---------------- helpers ----------------
__device__ __forceinline__ float softplus_f(float x) {
    return fmaxf(x, 0.0f) + log1pf(expf(-fabsf(x)));
}
__device__ __forceinline__ uint32_t smem_u32(const void* p) {
    return (uint32_t)__cvta_generic_to_shared(p);
}
__device__ __forceinline__ void ldm_x4(uint32_t* r, uint32_t addr) {
    asm volatile("ldmatrix.sync.aligned.m8n8.x4.shared.b16 {%0,%1,%2,%3}, [%4];"
                 : "=r"(r[0]), "=r"(r[1]), "=r"(r[2]), "=r"(r[3]) : "r"(addr));
}
__device__ __forceinline__ void mma16816(float* c, const uint32_t* a, const uint32_t* b) {
    asm volatile(
        "mma.sync.aligned.m16n8k16.row.col.f32.bf16.bf16.f32 "
        "{%0,%1,%2,%3}, {%4,%5,%6,%7}, {%8,%9}, {%0,%1,%2,%3};"
        : "+f"(c[0]), "+f"(c[1]), "+f"(c[2]), "+f"(c[3])
        : "r"(a[0]), "r"(a[1]), "r"(a[2]), "r"(a[3]), "r"(b[0]), "r"(b[1]));
}
__device__ __forceinline__ void cp16(uint32_t dst, const void* src, int srcsize) {
    asm volatile("cp.async.cg.shared.global [%0], [%1], 16, %2;\n"
                 :: "r"(dst), "l"(src), "r"(srcsize));
}
__device__ __forceinline__ void cp_commit() {
    asm volatile("cp.async.commit_group;\n");
}
template <int N>
__device__ __forceinline__ void cp_wait() {
    asm volatile("cp.async.wait_group %0;\n" :: "n"(N));
}

// ---------------- fp32 -> (bf16 hi, bf16 lo) splits ----------------
__global__ void split_data_kernel(const float* __restrict__ x) {
    int i = blockIdx.x * 256 + threadIdx.x;
    if (i < Bb * Tt * Cc) {
        float v = x[i];
        __nv_bfloat16 h = __float2bfloat16(v);
        g_dhi[i] = h;
        g_dlo[i] = __float2bfloat16(v - __bfloat162float(h));
    }
}
__global__ void split_w1_kernel(const float* __restrict__ x) {
    int i = blockIdx.x * 256 + threadIdx.x;
    if (i < Ee * 256 * Cc) {
        float v = x[i];
        __nv_bfloat16 h = __float2bfloat16(v);
        g_w1hi[i] = h;
        g_w1lo[i] = __float2bfloat16(v - __bfloat162float(h));
    }
}

// ---------------- generic 32x64 SGEMM with register prefetch (K=512) ----------------
__device__ __forceinline__ void sgemm_body32(const float* __restrict__ A, int lda,
                                             const float* __restrict__ W,
                                             const float* __restrict__ bias,
                                             float* __restrict__ C, int ldc,
                                             float alpha, int n0, int m0) {
    __shared__ float As[16 * 36];
    __shared__ float Ws[16 * 68];
    int tid = threadIdx.x;
    int ty = tid >> 4, tx = tid & 15;
    float acc[2][4] = {};
    float ar[2], wr[4];
#pragma unroll
    for (int r = 0; r < 2; r++) { int l = r * 256 + tid; int m = l >> 4, kc = l & 15; ar[r] = A[(m0 + m) * lda + kc]; }
#pragma unroll
    for (int r = 0; r < 4; r++) { int l = r * 256 + tid; int n = l >> 4, kc = l & 15; wr[r] = W[(n0 + n) * 512 + kc]; }
    for (int kk = 0; kk < 512; kk += 16) {
#pragma unroll
        for (int r = 0; r < 2; r++) { int l = r * 256 + tid; int m = l >> 4, kc = l & 15; As[kc * 36 + m] = ar[r]; }
#pragma unroll
        for (int r = 0; r < 4; r++) { int l = r * 256 + tid; int n = l >> 4, kc = l & 15; Ws[kc * 68 + n] = wr[r]; }
        __syncthreads();
        if (kk + 16 < 512) {
#pragma unroll
            for (int r = 0; r < 2; r++) { int l = r * 256 + tid; int m = l >> 4, kc = l & 15; ar[r] = A[(m0 + m) * lda + kk + 16 + kc]; }
#pragma unroll
            for (int r = 0; r < 4; r++) { int l = r * 256 + tid; int n = l >> 4, kc = l & 15; wr[r] = W[(n0 + n) * 512 + kk + 16 + kc]; }
        }
#pragma unroll
        for (int kc = 0; kc < 16; kc++) {
            float a0 = As[kc * 36 + ty * 2];
            float a1 = As[kc * 36 + ty * 2 + 1];
            float4 bv = *(const float4*)&Ws[kc * 68 + tx * 4];
            acc[0][0] += a0 * bv.x; acc[0][1] += a0 * bv.y;
            acc[0][2] += a0 * bv.z; acc[0][3] += a0 * bv.w;
            acc[1][0] += a1 * bv.x; acc[1][1] += a1 * bv.y;
            acc[1][2] += a1 * bv.z; acc[1][3] += a1 * bv.w;
        }
        __syncthreads();
    }
#pragma unroll
    for (int i = 0; i < 2; i++) {
        int m = m0 + ty * 2 + i;
#pragma unroll
        for (int j = 0; j < 4; j++) {
            int n = n0 + tx * 4 + j;
            C[m * ldc + n] = alpha * (acc[i][j] + bias[n]);
        }
    }
}
__global__ void proj_q_kernel(const float* __restrict__ qst,
                              const float* __restrict__ ipw,
                              const float* __restrict__ ipb) {
    sgemm_body32(qst, 512, ipw, ipb, g_q, 512, 0.125f, blockIdx.x * 64, blockIdx.y * 32);
}
__global__ void proj_tmp_kernel(const float* __restrict__ opw,
                                const float* __restrict__ opb) {
    sgemm_body32(g_ctx, 512, opw, opb, g_tmp, 512, 1.0f, blockIdx.x * 64, blockIdx.y * 32);
}
// ctx_h[B,64] = pd_h[B,512] @ Wv_h[64,512]^T + bv_h  (per head)
__global__ void ctx_kernel(const float* __restrict__ ipw,
                           const float* __restrict__ ipb) {
    int h = blockIdx.x;
    sgemm_body32(g_pd + h * 512, Hh * 512,
                 ipw + (1024 + h * 64) * 512,
                 ipb + 1024 + h * 64,
                 g_ctx + h * 64, 512, 1.0f, 0, blockIdx.y * 32);
}

// ---------------- rk = q_h @ Wk_h : 8 GEMMs of [256 x 512 x 64] ----------------
__global__ void rk_kernel(const float* __restrict__ ipw) {
    __shared__ float As[16 * 68];
    __shared__ float Ws[16 * 68];
    int n0 = blockIdx.x * 64, m0 = blockIdx.y * 64, h = blockIdx.z;
    int tid = threadIdx.x, ty = tid >> 4, tx = tid & 15;
    float acc[4][4] = {};
    for (int kk = 0; kk < 64; kk += 16) {
#pragma unroll
        for (int r = 0; r < 4; r++) {
            int l = r * 256 + tid;
            int m = l >> 4, kc = l & 15;
            As[kc * 68 + m] = g_q[(m0 + m) * 512 + h * 64 + kk + kc];
        }
#pragma unroll
        for (int r = 0; r < 4; r++) {
            int l = r * 256 + tid;
            int kc = l >> 6, n = l & 63;
            Ws[kc * 68 + n] = ipw[(512 + h * 64 + kk + kc) * 512 + n0 + n];
        }
        __syncthreads();
#pragma unroll
        for (int kc = 0; kc < 16; kc++) {
            float4 av = *(const float4*)&As[kc * 68 + ty * 4];
            float4 bv = *(const float4*)&Ws[kc * 68 + tx * 4];
            float a[4] = {av.x, av.y, av.z, av.w};
            float b[4] = {bv.x, bv.y, bv.z, bv.w};
#pragma unroll
            for (int i = 0; i < 4; i++)
#pragma unroll
                for (int j = 0; j < 4; j++) acc[i][j] += a[i] * b[j];
        }
        __syncthreads();
    }
#pragma unroll
    for (int i = 0; i < 4; i++) {
        int b = m0 + ty * 4 + i;
#pragma unroll
        for (int j = 0; j < 4; j++)
            g_rk[(b * Hh + h) * 512 + n0 + tx * 4 + j] = acc[i][j];
    }
}

// ---------------- attention per b: scores (8 heads/share data reads) + softmax + pooled pd ----------------
__global__ void attn_kernel(const float* __restrict__ data,
                            const float* __restrict__ ipb) {
    int b = blockIdx.x, tid = threadIdx.x;
    __shared__ float rks[8 * 512];
    __shared__ float scr[8][64];
    __shared__ float qb_s[8];
    const float* rkg = g_rk + b * (Hh * 512);
    for (int i = tid * 4; i < 4096; i += 1024)
        *(float4*)&rks[i] = *(const float4*)&rkg[i];
    if (tid < 32) scr[tid >> 2][60 + (tid & 3)] = -1e30f;
    int w = tid >> 5, lane = tid & 31;
    // qb[h] = q[b,h,:] . bk_h   (warp w handles head w)
    {
        float s = g_q[b * 512 + w * 64 + lane] * ipb[512 + w * 64 + lane]
                + g_q[b * 512 + w * 64 + 32 + lane] * ipb[512 + w * 64 + 32 + lane];
#pragma unroll
        for (int o = 16; o > 0; o >>= 1) s += __shfl_down_sync(0xffffffffu, s, o);
        if (lane == 0) qb_s[w] = s;
    }
    __syncthreads();
    // scores
    for (int t = w; t < Tt; t += 8) {
        const float* dp = data + (b * Tt + t) * 512;
        float part[8] = {};
#pragma unroll
        for (int j = 0; j < 4; j++) {
            float4 d4 = *(const float4*)&dp[j * 128 + lane * 4];
#pragma unroll
            for (int h = 0; h < 8; h++) {
                float4 r4 = *(const float4*)&rks[h * 512 + j * 128 + lane * 4];
                part[h] += d4.x * r4.x + d4.y * r4.y + d4.z * r4.z + d4.w * r4.w;
            }
        }
#pragma unroll
        for (int h = 0; h < 8; h++) {
            float s = part[h];
#pragma unroll
            for (int o = 16; o > 0; o >>= 1) s += __shfl_down_sync(0xffffffffu, s, o);
            if (lane == 0) scr[h][t] = s + qb_s[h];
        }
    }
    __syncthreads();
    // softmax per head (warp w = head w)
    {
        float v0 = scr[w][lane];
        float v1 = scr[w][lane + 32];
        float m = fmaxf(v0, v1);
#pragma unroll
        for (int o = 16; o > 0; o >>= 1) m = fmaxf(m, __shfl_xor_sync(0xffffffffu, m, o));
        float e0 = (lane < Tt) ? expf(v0 - m) : 0.0f;
        float e1 = (lane + 32 < Tt) ? expf(v1 - m) : 0.0f;
        float s = e0 + e1;
#pragma unroll
        for (int o = 16; o > 0; o >>= 1) s += __shfl_xor_sync(0xffffffffu, s, o);
        float inv = 1.0f / s;
        scr[w][lane] = e0 * inv;
        scr[w][lane + 32] = e1 * inv;
    }
    __syncthreads();
    // pd[h,c] = sum_t p[h,t] * data[b,t,c]
    float acc[8][2] = {};
    const float* dpb = data + b * Tt * 512;
    for (int t = 0; t < Tt; t++) {
        float d0 = dpb[t * 512 + tid];
        float d1 = dpb[t * 512 + tid + 256];
#pragma unroll
        for (int h = 0; h < 8; h++) {
            float p = scr[h][t];
            acc[h][0] += p * d0;
            acc[h][1] += p * d1;
        }
    }
#pragma unroll
    for (int h = 0; h < 8; h++) {
        g_pd[(b * Hh + h) * 512 + tid] = acc[h][0];
        g_pd[(b * Hh + h) * 512 + tid + 256] = acc[h][1];
    }
}

// ---------------- router + top-k + beta time weights ----------------
__global__ void router_kernel(const float* __restrict__ router_w,
                              const float* __restrict__ router_b,
                              const float* __restrict__ beta_w,
                              const float* __restrict__ beta_b) {
    int b = blockIdx.x;
    __shared__ float tmp_s[512];
    __shared__ float logit[32];
    __shared__ float al[Ee], be[Ee];
    __shared__ int sel_i[Kk];
    __shared__ float w_s[Kk * Tt];
    int tid = threadIdx.x;
    for (int c = tid; c < 512; c += 256) tmp_s[c] = g_tmp[b * Cc + c];
    __syncthreads();
    int w = tid >> 5, lane = tid & 31;
    for (int r = w; r < 30; r += 8) {
        const float* wr; float bias;
        if (r < Ee) { wr = router_w + r * 512; bias = router_b[r]; }
        else { wr = beta_w + (r - Ee) * 512; bias = beta_b[r - Ee]; }
        float s = 0.f;
        for (int c = lane; c < 512; c += 32) s += wr[c] * tmp_s[c];
#pragma unroll
        for (int o = 16; o > 0; o >>= 1) s += __shfl_down_sync(0xffffffffu, s, o);
        if (lane == 0) logit[r] = s + bias;
    }
    __syncthreads();
    if (tid < Ee) {
        al[tid] = softplus_f(logit[Ee + 2 * tid]) + 1e-6f;
        be[tid] = softplus_f(logit[Ee + 2 * tid + 1]) + 1e-6f;
    }
    if (tid == 0) {
        float m = logit[0];
        for (int e = 1; e < Ee; e++) m = fmaxf(m, logit[e]);
        float pe[Ee]; float s = 0.f;
        for (int e = 0; e < Ee; e++) { pe[e] = expf(logit[e] - m); s += pe[e]; }
        float invs = 1.0f / s;
        for (int e = 0; e < Ee; e++) pe[e] *= invs;
        bool used[Ee] = {};
        float psum = 0.f; float sp[Kk];
        for (int kk = 0; kk < Kk; kk++) {
            int best = 0; float bv = -1.f;
            for (int e = 0; e < Ee; e++)
                if (!used[e] && pe[e] > bv) { bv = pe[e]; best = e; }
            used[best] = true; sel_i[kk] = best; sp[kk] = bv; psum += bv;
        }
        float inv = 1.0f / (psum + 1e-8f);
        for (int kk = 0; kk < Kk; kk++) {
            g_topk_i[b * Kk + kk] = sel_i[kk];
            g_topk_p[b * Kk + kk] = sp[kk] * inv;
        }
    }
    __syncthreads();
    for (int i = tid; i < Kk * Tt; i += 256) {
        int kk = i / Tt, t = i % Tt;
        int e = sel_i[kk];
        float a = al[e], bb = be[e];
        float tt = (float)t / 59.0f;
        float lt = logf(tt + 1e-12f);
        float l1 = logf(1.0f - tt + 1e-12f);
        float norm = lgammaf(a) + lgammaf(bb) - lgammaf(a + bb);
        w_s[i] = expf((a - 1.0f) * lt + (bb - 1.0f) * l1 - norm);
    }
    __syncthreads();
    if (tid < Kk) {
        float m = 0.f;
        for (int t = 0; t < Tt; t++) m = fmaxf(m, w_s[tid * Tt + t]);
        float inv = 1.0f / (m + 1e-8f);
        float s = 0.f;
        for (int t = 0; t < Tt; t++) {
            float v = w_s[tid * Tt + t] * inv;
            g_tw[(b * Kk + tid) * Tt + t] = v;
            s += v;
        }
        g_sw[b * Kk + tid] = s;
    }
}

// ---------------- build per-expert pair lists ----------------
__global__ void build_groups_kernel() {
    __shared__ int scnt[Ee];
    int tid = threadIdx.x;
    if (tid < Ee) scnt[tid] = 0;
    __syncthreads();
    for (int bk = tid; bk < Bb * Kk; bk += 256) {
        int e = g_topk_i[bk];
        int slot = atomicAdd(&scnt[e], 1);
        g_glist[e * 256 + slot] = bk;
    }
    __syncthreads();
    if (tid < Ee) g_cnt[tid] = scnt[tid];
}

// ---------------- layer1 via tensor cores, cp.async double-buffered ----------------
__global__ void layer1_mma_kernel(const float* __restrict__ b1) {
    __shared__ __nv_bfloat16 As[2][64 * 72];
    __shared__ __nv_bfloat16 Bs[2][64 * 72];
    __shared__ float tw_s[64];
    __shared__ float red[4 * 68];
    int bk = blockIdx.y;
    int b = bk / Kk;
    int n0blk = blockIdx.x * 64;
    int e = g_topk_i[bk];
    int tid = threadIdx.x;
    int warp = tid >> 5, lane = tid & 31;
    int mw = warp >> 1, nw = warp & 1;

    if (tid < 64) tw_s[tid] = (tid < Tt) ? g_tw[bk * Tt + tid] : 0.0f;

    long aoff = (long)b * (Tt * Cc);
    long boff = (long)e * (256 * Cc) + (long)n0blk * Cc;
    const __nv_bfloat16* Aseg[3];
    const __nv_bfloat16* Bseg[3];
    Aseg[0] = g_dhi + aoff;  Bseg[0] = g_w1hi + boff;
    Aseg[1] = g_dlo + aoff;  Bseg[1] = g_w1hi + boff;
    Aseg[2] = g_dhi + aoff;  Bseg[2] = g_w1lo + boff;

    int row0 = tid >> 3, c0 = (tid & 7) * 8;
    int row1 = (256 + tid) >> 3, c1 = c0;

    auto issue = [&](int ch, int buf) {
        int seg = ch >> 3;
        int kb = (ch & 7) * 64;
        const __nv_bfloat16* Ap = Aseg[seg];
        const __nv_bfloat16* Bp = Bseg[seg];
        const __nv_bfloat16* a0 = (row0 < Tt) ? (Ap + row0 * Cc + kb + c0) : Ap;
        const __nv_bfloat16* a1 = (row1 < Tt) ? (Ap + row1 * Cc + kb + c1) : Ap;
        cp16(smem_u32(&As[buf][row0 * 72 + c0]), a0, row0 < Tt ? 16 : 0);
        cp16(smem_u32(&Bs[buf][row0 * 72 + c0]), Bp + row0 * Cc + kb + c0, 16);
        cp16(smem_u32(&As[buf][row1 * 72 + c1]), a1, row1 < Tt ? 16 : 0);
        cp16(smem_u32(&Bs[buf][row1 * 72 + c1]), Bp + row1 * Cc + kb + c1, 16);
        cp_commit();
    };

    float acc[4][4] = {};
    issue(0, 0);
    for (int ch = 0; ch < 24; ch++) {
        int cur = ch & 1;
        if (ch < 23) { issue(ch + 1, cur ^ 1); cp_wait<1>(); }
        else { cp_wait<0>(); }
        __syncthreads();
#pragma unroll
        for (int ks = 0; ks < 4; ks++) {
            uint32_t a[4];
            int arow = mw * 16 + (lane & 15);
            int acol = ks * 16 + (lane >> 4) * 8;
            ldm_x4(a, smem_u32(&As[cur][arow * 72 + acol]));
            uint32_t bf[8];
#pragma unroll
            for (int half = 0; half < 2; half++) {
                int nbase = nw * 32 + half * 16;
                int grp = lane >> 3, l8 = lane & 7;
                int nrow = nbase + (grp >> 1) * 8 + l8;
                int kcol = ks * 16 + (grp & 1) * 8;
                ldm_x4(bf + half * 4, smem_u32(&Bs[cur][nrow * 72 + kcol]));
            }
#pragma unroll
            for (int j = 0; j < 4; j++) mma16816(acc[j], a, bf + j * 2);
        }
        __syncthreads();
    }
    int g = lane >> 2, t4 = lane & 3;
    int r0 = mw * 16 + g, r1 = r0 + 8;
    float w0 = tw_s[r0], w1 = tw_s[r1];
#pragma unroll
    for (int j = 0; j < 4; j++) {
        int nc0 = nw * 32 + j * 8 + t4 * 2;
        float bias0 = b1[e * 256 + n0blk + nc0];
        float bias1 = b1[e * 256 + n0blk + nc0 + 1];
        float s0 = w0 * fmaxf(acc[j][0] + bias0, 0.f) + w1 * fmaxf(acc[j][2] + bias0, 0.f);
        float s1 = w0 * fmaxf(acc[j][1] + bias1, 0.f) + w1 * fmaxf(acc[j][3] + bias1, 0.f);
#pragma unroll
        for (int o = 16; o >= 4; o >>= 1) {
            s0 += __shfl_down_sync(0xffffffffu, s0, o);
            s1 += __shfl_down_sync(0xffffffffu, s1, o);
        }
        if (g == 0) {
            red[mw * 68 + nc0] = s0;
            red[mw * 68 + nc0 + 1] = s1;
        }
    }
    __syncthreads();
    if (tid < 64) {
        float p = red[tid] + red[68 + tid] + red[136 + tid] + red[204 + tid];
        g_pooled[bk * 256 + n0blk + tid] = p;
    }
}

// ---------------- layer2: expert-grouped GEMM [n_e x 512 x 256] ----------------
__global__ void layer2_kernel(const float* __restrict__ w2,
                              const float* __restrict__ b2) {
    int nt = blockIdx.x, mt = blockIdx.y, e = blockIdx.z;
    int cnt = g_cnt[e];
    if (mt * 32 >= cnt) return;
    __shared__ float P[32 * 260];
    __shared__ float Ws[64 * 65];
    __shared__ int prs[32];
    int tid = threadIdx.x;
    int rows = cnt - mt * 32; if (rows > 32) rows = 32;
    if (tid < 32) prs[tid] = (tid < rows) ? g_glist[e * 256 + mt * 32 + tid] : -1;
    __syncthreads();
#pragma unroll
    for (int r = 0; r < 8; r++) {
        int fi = r * 256 + tid;
        int row = fi >> 6, c4 = (fi & 63) * 4;
        float4 v = make_float4(0.f, 0.f, 0.f, 0.f);
        int p = prs[row];
        if (p >= 0) v = *(const float4*)&g_pooled[p * 256 + c4];
        *(float4*)&P[row * 260 + c4] = v;
    }
    int nn = tid & 31, mg = tid >> 5;
    float acc[4][2] = {};
    for (int q = 0; q < 4; q++) {
        __syncthreads();
#pragma unroll
        for (int r = 0; r < 16; r++) {
            int fi = r * 256 + tid;
            int n = fi >> 6, kc = fi & 63;
            Ws[n * 65 + kc] = w2[(e * 512 + nt * 64 + n) * 256 + q * 64 + kc];
        }
        __syncthreads();
#pragma unroll 4
        for (int kc = 0; kc < 64; kc++) {
            float w0 = Ws[nn * 65 + kc];
            float w1 = Ws[(nn + 32) * 65 + kc];
#pragma unroll
            for (int mi = 0; mi < 4; mi++) {
                float pv = P[(mg + mi * 8) * 260 + q * 64 + kc];
                acc[mi][0] += pv * w0;
                acc[mi][1] += pv * w1;
            }
        }
    }
#pragma unroll
    for (int mi = 0; mi < 4; mi++) {
        int row = mg + mi * 8;
        int p = prs[row];
        if (p >= 0) {
            float sw = g_sw[p];
            int cc0 = nt * 64 + nn, cc1 = cc0 + 32;
            g_perexp[p * 512 + cc0] = acc[mi][0] + sw * b2[e * 512 + cc0];
            g_perexp[p * 512 + cc1] = acc[mi][1] + sw * b2[e * 512 + cc1];
        }
    }
}

// ---------------- combine + LayerNorm ----------------
__global__ void ln_kernel(const float* __restrict__ ln_g,
                          const float* __restrict__ ln_b,
                          float* __restrict__ out) {
    int b = blockIdx.x, tid = threadIdx.x;
    __shared__ float red[18];
    float y0 = 0.f, y1 = 0.f;
#pragma unroll
    for (int kk = 0; kk < Kk; kk++) {
        float p = g_topk_p[b * Kk + kk];
        const float* pe = g_perexp + (b * Kk + kk) * 512;
        y0 += p * pe[tid];
        y1 += p * pe[tid + 256];
    }
    float s = y0 + y1, sq = y0 * y0 + y1 * y1;
    int w = tid >> 5, lane = tid & 31;
#pragma unroll
    for (int o = 16; o > 0; o >>= 1) {
        s += __shfl_down_sync(0xffffffffu, s, o);
        sq += __shfl_down_sync(0xffffffffu, sq, o);
    }
    if (lane == 0) { red[w] = s; red[8 + w] = sq; }
    __syncthreads();
    if (tid == 0) {
        float S = 0.f, SQ = 0.f;
        for (int i = 0; i < 8; i++) { S += red[i]; SQ += red[8 + i]; }
        red[16] = S; red[17] = SQ;
    }
    __syncthreads();
    float mean = red[16] * (1.0f / 512.0f);
    float var = red[17] * (1.0f / 512.0f) - mean * mean;
    float rstd = rsqrtf(var + 1e-5f);
    out[b * Cc + tid] = (y0 - mean) * rstd * ln_g[tid] + ln_b[tid];
    out[b * Cc + tid + 256] = (y1 - mean) * rstd * ln_g[tid + 256] + ln_b[tid + 256];
}

// ---------------- launch ----------------
extern "C" void kernel_launch(void* const* d_in, const int* in_sizes, int n_in,
                              void* d_out, int out_size) {
    const float* qst = (const float*)d_in[0];
    const float* data = (const float*)d_in[1];
    const float* ipw = (const float*)d_in[2];
    const float* ipb = (const float*)d_in[3];
    const float* opw = (const float*)d_in[4];
    const float* opb = (const float*)d_in[5];
    const float* rw  = (const float*)d_in[6];
    const float* rb  = (const float*)d_in[7];
    const float* bw  = (const float*)d_in[8];
    const float* bb  = (const float*)d_in[9];
    const float* w1  = (const float*)d_in[10];
    const float* b1  = (const float*)d_in[11];
    const float* w2  = (const float*)d_in[12];
    const float* b2  = (const float*)d_in[13];
    const float* lng = (const float*)d_in[14];
    const float* lnb = (const float*)d_in[15];
    float* out = (float*)d_out;

    split_data_kernel<<<(Bb * Tt * Cc + 255) / 256, 256>>>(data);
    split_w1_kernel<<<(Ee * 256 * Cc + 255) / 256, 256>>>(w1);
    proj_q_kernel<<<dim3(8, 8), 256>>>(qst, ipw, ipb);
    rk_kernel<<<dim3(8, 4, 8), 256>>>(ipw);
    attn_kernel<<<Bb, 256>>>(data, ipb);
    ctx_kernel<<<dim3(8, 8), 256>>>(ipw, ipb);
    proj_tmp_kernel<<<dim3(8, 8), 256>>>(opw, opb);
    router_kernel<<<Bb, 256>>>(rw, rb, bw, bb);
    build_groups_kernel<<<1, 256>>>();
    layer1_mma_kernel<<<dim3(4, Bb * Kk), 256>>>(b1);
    layer2_kernel<<<dim3(8, 8, Ee), 256>>>(w2, b2);
    ln_kernel<<<Bb, 256>>>(lng, lnb, out);
}

// round 8
// speedup vs baseline: 2.4275x; 1.2753x over previous
#include <cuda_runtime.h>
#include <cuda_fp16.h>
#include <cstdint>
#include <math.h>

#define Bb 256
#define Tt 60
#define Cc 512
#define Ee 10
#define Kk 5
#define Hh 8
#define DH 64

// ---------------- scratch (device globals) ----------------
__device__ float g_q[Bb * Cc];
__device__ float g_rk[Bb * Hh * Cc];
__device__ float g_ctx[Bb * Cc];
__device__ float g_tmp[Bb * Cc];
__device__ int   g_topk_i[Bb * Kk];
__device__ float g_topk_p[Bb * Kk];
__device__ float g_tw[Bb * Kk * Tt];
__device__ float g_sw[Bb * Kk];
__device__ float g_pooled[Bb * Kk * 256];
__device__ float g_pd[Bb * Hh * Cc];
__device__ float g_perexp[Bb * Kk * Cc];
__device__ int   g_glist[Ee * 256];
__device__ int   g_cnt[Ee];
// fp16 splits: A = hi + lo (exact to ~2^-22); W1 single fp16 term
__device__ __half g_dhi[Bb * Tt * Cc];
__device__ __half g_dlo[Bb * Tt * Cc];
__device__ __half g_w1h[Ee * 256 * Cc];

// ---------------- helpers ----------------
__device__ __forceinline__ float softplus_f(float x) {
    return fmaxf(x, 0.0f) + log1pf(expf(-fabsf(x)));
}
__device__ __forceinline__ uint32_t smem_u32(const void* p) {
    return (uint32_t)__cvta_generic_to_shared(p);
}
__device__ __forceinline__ void ldm_x4(uint32_t* r, uint32_t addr) {
    asm volatile("ldmatrix.sync.aligned.m8n8.x4.shared.b16 {%0,%1,%2,%3}, [%4];"
                 : "=r"(r[0]), "=r"(r[1]), "=r"(r[2]), "=r"(r[3]) : "r"(addr));
}
__device__ __forceinline__ void mma16816(float* c, const uint32_t* a, const uint32_t* b) {
    asm volatile(
        "mma.sync.aligned.m16n8k16.row.col.f32.f16.f16.f32 "
        "{%0,%1,%2,%3}, {%4,%5,%6,%7}, {%8,%9}, {%0,%1,%2,%3};"
        : "+f"(c[0]), "+f"(c[1]), "+f"(c[2]), "+f"(c[3])
        : "r"(a[0]), "r"(a[1]), "r"(a[2]), "r"(a[3]), "r"(b[0]), "r"(b[1]));
}
__device__ __forceinline__ void cp16(uint32_t dst, const void* src, int srcsize) {
    asm volatile("cp.async.cg.shared.global [%0], [%1], 16, %2;\n"
                 :: "r"(dst), "l"(src), "r"(srcsize));
}
__device__ __forceinline__ void cp_commit() {
    asm volatile("cp.async.commit_group;\n");
}
template <int N>
__device__ __forceinline__ void cp_wait() {
    asm volatile("cp.async.wait_group %0;\n" :: "n"(N));
}

// ---------------- fp32 -> (fp16 hi, fp16 lo) split for data; fp16 for W1 ----------------
__global__ void split_data_kernel(const float* __restrict__ x) {
    int i = blockIdx.x * 256 + threadIdx.x;
    if (i < Bb * Tt * Cc) {
        float v = x[i];
        __half h = __float2half_rn(v);
        g_dhi[i] = h;
        g_dlo[i] = __float2half_rn(v - __half2float(h));
    }
}
__global__ void split_w1_kernel(const float* __restrict__ x) {
    int i = blockIdx.x * 256 + threadIdx.x;
    if (i < Ee * 256 * Cc) g_w1h[i] = __float2half_rn(x[i]);
}

// ---------------- generic 32x64 SGEMM with register prefetch (K=512) ----------------
__device__ __forceinline__ void sgemm_body32(const float* __restrict__ A, int lda,
                                             const float* __restrict__ W,
                                             const float* __restrict__ bias,
                                             float* __restrict__ C, int ldc,
                                             float alpha, int n0, int m0) {
    __shared__ float As[16 * 36];
    __shared__ float Ws[16 * 68];
    int tid = threadIdx.x;
    int ty = tid >> 4, tx = tid & 15;
    float acc[2][4] = {};
    float ar[2], wr[4];
#pragma unroll
    for (int r = 0; r < 2; r++) { int l = r * 256 + tid; int m = l >> 4, kc = l & 15; ar[r] = A[(m0 + m) * lda + kc]; }
#pragma unroll
    for (int r = 0; r < 4; r++) { int l = r * 256 + tid; int n = l >> 4, kc = l & 15; wr[r] = W[(n0 + n) * 512 + kc]; }
    for (int kk = 0; kk < 512; kk += 16) {
#pragma unroll
        for (int r = 0; r < 2; r++) { int l = r * 256 + tid; int m = l >> 4, kc = l & 15; As[kc * 36 + m] = ar[r]; }
#pragma unroll
        for (int r = 0; r < 4; r++) { int l = r * 256 + tid; int n = l >> 4, kc = l & 15; Ws[kc * 68 + n] = wr[r]; }
        __syncthreads();
        if (kk + 16 < 512) {
#pragma unroll
            for (int r = 0; r < 2; r++) { int l = r * 256 + tid; int m = l >> 4, kc = l & 15; ar[r] = A[(m0 + m) * lda + kk + 16 + kc]; }
#pragma unroll
            for (int r = 0; r < 4; r++) { int l = r * 256 + tid; int n = l >> 4, kc = l & 15; wr[r] = W[(n0 + n) * 512 + kk + 16 + kc]; }
        }
#pragma unroll
        for (int kc = 0; kc < 16; kc++) {
            float a0 = As[kc * 36 + ty * 2];
            float a1 = As[kc * 36 + ty * 2 + 1];
            float4 bv = *(const float4*)&Ws[kc * 68 + tx * 4];
            acc[0][0] += a0 * bv.x; acc[0][1] += a0 * bv.y;
            acc[0][2] += a0 * bv.z; acc[0][3] += a0 * bv.w;
            acc[1][0] += a1 * bv.x; acc[1][1] += a1 * bv.y;
            acc[1][2] += a1 * bv.z; acc[1][3] += a1 * bv.w;
        }
        __syncthreads();
    }
#pragma unroll
    for (int i = 0; i < 2; i++) {
        int m = m0 + ty * 2 + i;
#pragma unroll
        for (int j = 0; j < 4; j++) {
            int n = n0 + tx * 4 + j;
            C[m * ldc + n] = alpha * (acc[i][j] + bias[n]);
        }
    }
}
__global__ void proj_q_kernel(const float* __restrict__ qst,
                              const float* __restrict__ ipw,
                              const float* __restrict__ ipb) {
    sgemm_body32(qst, 512, ipw, ipb, g_q, 512, 0.125f, blockIdx.x * 64, blockIdx.y * 32);
}
__global__ void proj_tmp_kernel(const float* __restrict__ opw,
                                const float* __restrict__ opb) {
    sgemm_body32(g_ctx, 512, opw, opb, g_tmp, 512, 1.0f, blockIdx.x * 64, blockIdx.y * 32);
}
__global__ void ctx_kernel(const float* __restrict__ ipw,
                           const float* __restrict__ ipb) {
    int h = blockIdx.x;
    sgemm_body32(g_pd + h * 512, Hh * 512,
                 ipw + (1024 + h * 64) * 512,
                 ipb + 1024 + h * 64,
                 g_ctx + h * 64, 512, 1.0f, 0, blockIdx.y * 32);
}

// ---------------- rk = q_h @ Wk_h : 8 GEMMs of [256 x 512 x 64] ----------------
__global__ void rk_kernel(const float* __restrict__ ipw) {
    __shared__ float As[16 * 68];
    __shared__ float Ws[16 * 68];
    int n0 = blockIdx.x * 64, m0 = blockIdx.y * 64, h = blockIdx.z;
    int tid = threadIdx.x, ty = tid >> 4, tx = tid & 15;
    float acc[4][4] = {};
    for (int kk = 0; kk < 64; kk += 16) {
#pragma unroll
        for (int r = 0; r < 4; r++) {
            int l = r * 256 + tid;
            int m = l >> 4, kc = l & 15;
            As[kc * 68 + m] = g_q[(m0 + m) * 512 + h * 64 + kk + kc];
        }
#pragma unroll
        for (int r = 0; r < 4; r++) {
            int l = r * 256 + tid;
            int kc = l >> 6, n = l & 63;
            Ws[kc * 68 + n] = ipw[(512 + h * 64 + kk + kc) * 512 + n0 + n];
        }
        __syncthreads();
#pragma unroll
        for (int kc = 0; kc < 16; kc++) {
            float4 av = *(const float4*)&As[kc * 68 + ty * 4];
            float4 bv = *(const float4*)&Ws[kc * 68 + tx * 4];
            float a[4] = {av.x, av.y, av.z, av.w};
            float b[4] = {bv.x, bv.y, bv.z, bv.w};
#pragma unroll
            for (int i = 0; i < 4; i++)
#pragma unroll
                for (int j = 0; j < 4; j++) acc[i][j] += a[i] * b[j];
        }
        __syncthreads();
    }
#pragma unroll
    for (int i = 0; i < 4; i++) {
        int b = m0 + ty * 4 + i;
#pragma unroll
        for (int j = 0; j < 4; j++)
            g_rk[(b * Hh + h) * 512 + n0 + tx * 4 + j] = acc[i][j];
    }
}

// ---------------- attention per b ----------------
__global__ void attn_kernel(const float* __restrict__ data,
                            const float* __restrict__ ipb) {
    int b = blockIdx.x, tid = threadIdx.x;
    __shared__ float rks[8 * 512];
    __shared__ float scr[8][64];
    __shared__ float qb_s[8];
    const float* rkg = g_rk + b * (Hh * 512);
    for (int i = tid * 4; i < 4096; i += 1024)
        *(float4*)&rks[i] = *(const float4*)&rkg[i];
    if (tid < 32) scr[tid >> 2][60 + (tid & 3)] = -1e30f;
    int w = tid >> 5, lane = tid & 31;
    {
        float s = g_q[b * 512 + w * 64 + lane] * ipb[512 + w * 64 + lane]
                + g_q[b * 512 + w * 64 + 32 + lane] * ipb[512 + w * 64 + 32 + lane];
#pragma unroll
        for (int o = 16; o > 0; o >>= 1) s += __shfl_down_sync(0xffffffffu, s, o);
        if (lane == 0) qb_s[w] = s;
    }
    __syncthreads();
    for (int t = w; t < Tt; t += 8) {
        const float* dp = data + (b * Tt + t) * 512;
        float part[8] = {};
#pragma unroll
        for (int j = 0; j < 4; j++) {
            float4 d4 = *(const float4*)&dp[j * 128 + lane * 4];
#pragma unroll
            for (int h = 0; h < 8; h++) {
                float4 r4 = *(const float4*)&rks[h * 512 + j * 128 + lane * 4];
                part[h] += d4.x * r4.x + d4.y * r4.y + d4.z * r4.z + d4.w * r4.w;
            }
        }
#pragma unroll
        for (int h = 0; h < 8; h++) {
            float s = part[h];
#pragma unroll
            for (int o = 16; o > 0; o >>= 1) s += __shfl_down_sync(0xffffffffu, s, o);
            if (lane == 0) scr[h][t] = s + qb_s[h];
        }
    }
    __syncthreads();
    {
        float v0 = scr[w][lane];
        float v1 = scr[w][lane + 32];
        float m = fmaxf(v0, v1);
#pragma unroll
        for (int o = 16; o > 0; o >>= 1) m = fmaxf(m, __shfl_xor_sync(0xffffffffu, m, o));
        float e0 = (lane < Tt) ? expf(v0 - m) : 0.0f;
        float e1 = (lane + 32 < Tt) ? expf(v1 - m) : 0.0f;
        float s = e0 + e1;
#pragma unroll
        for (int o = 16; o > 0; o >>= 1) s += __shfl_xor_sync(0xffffffffu, s, o);
        float inv = 1.0f / s;
        scr[w][lane] = e0 * inv;
        scr[w][lane + 32] = e1 * inv;
    }
    __syncthreads();
    float acc[8][2] = {};
    const float* dpb = data + b * Tt * 512;
    for (int t = 0; t < Tt; t++) {
        float d0 = dpb[t * 512 + tid];
        float d1 = dpb[t * 512 + tid + 256];
#pragma unroll
        for (int h = 0; h < 8; h++) {
            float p = scr[h][t];
            acc[h][0] += p * d0;
            acc[h][1] += p * d1;
        }
    }
#pragma unroll
    for (int h = 0; h < 8; h++) {
        g_pd[(b * Hh + h) * 512 + tid] = acc[h][0];
        g_pd[(b * Hh + h) * 512 + tid + 256] = acc[h][1];
    }
}

// ---------------- router + top-k + beta time weights ----------------
__global__ void router_kernel(const float* __restrict__ router_w,
                              const float* __restrict__ router_b,
                              const float* __restrict__ beta_w,
                              const float* __restrict__ beta_b) {
    int b = blockIdx.x;
    __shared__ float tmp_s[512];
    __shared__ float logit[32];
    __shared__ float al[Ee], be[Ee];
    __shared__ int sel_i[Kk];
    __shared__ float w_s[Kk * Tt];
    int tid = threadIdx.x;
    for (int c = tid; c < 512; c += 256) tmp_s[c] = g_tmp[b * Cc + c];
    __syncthreads();
    int w = tid >> 5, lane = tid & 31;
    for (int r = w; r < 30; r += 8) {
        const float* wr; float bias;
        if (r < Ee) { wr = router_w + r * 512; bias = router_b[r]; }
        else { wr = beta_w + (r - Ee) * 512; bias = beta_b[r - Ee]; }
        float s = 0.f;
        for (int c = lane; c < 512; c += 32) s += wr[c] * tmp_s[c];
#pragma unroll
        for (int o = 16; o > 0; o >>= 1) s += __shfl_down_sync(0xffffffffu, s, o);
        if (lane == 0) logit[r] = s + bias;
    }
    __syncthreads();
    if (tid < Ee) {
        al[tid] = softplus_f(logit[Ee + 2 * tid]) + 1e-6f;
        be[tid] = softplus_f(logit[Ee + 2 * tid + 1]) + 1e-6f;
    }
    if (tid == 0) {
        float m = logit[0];
        for (int e = 1; e < Ee; e++) m = fmaxf(m, logit[e]);
        float pe[Ee]; float s = 0.f;
        for (int e = 0; e < Ee; e++) { pe[e] = expf(logit[e] - m); s += pe[e]; }
        float invs = 1.0f / s;
        for (int e = 0; e < Ee; e++) pe[e] *= invs;
        bool used[Ee] = {};
        float psum = 0.f; float sp[Kk];
        for (int kk = 0; kk < Kk; kk++) {
            int best = 0; float bv = -1.f;
            for (int e = 0; e < Ee; e++)
                if (!used[e] && pe[e] > bv) { bv = pe[e]; best = e; }
            used[best] = true; sel_i[kk] = best; sp[kk] = bv; psum += bv;
        }
        float inv = 1.0f / (psum + 1e-8f);
        for (int kk = 0; kk < Kk; kk++) {
            g_topk_i[b * Kk + kk] = sel_i[kk];
            g_topk_p[b * Kk + kk] = sp[kk] * inv;
        }
    }
    __syncthreads();
    for (int i = tid; i < Kk * Tt; i += 256) {
        int kk = i / Tt, t = i % Tt;
        int e = sel_i[kk];
        float a = al[e], bb = be[e];
        float tt = (float)t / 59.0f;
        float lt = logf(tt + 1e-12f);
        float l1 = logf(1.0f - tt + 1e-12f);
        float norm = lgammaf(a) + lgammaf(bb) - lgammaf(a + bb);
        w_s[i] = expf((a - 1.0f) * lt + (bb - 1.0f) * l1 - norm);
    }
    __syncthreads();
    if (tid < Kk) {
        float m = 0.f;
        for (int t = 0; t < Tt; t++) m = fmaxf(m, w_s[tid * Tt + t]);
        float inv = 1.0f / (m + 1e-8f);
        float s = 0.f;
        for (int t = 0; t < Tt; t++) {
            float v = w_s[tid * Tt + t] * inv;
            g_tw[(b * Kk + tid) * Tt + t] = v;
            s += v;
        }
        g_sw[b * Kk + tid] = s;
    }
}

// ---------------- build per-expert pair lists ----------------
__global__ void build_groups_kernel() {
    __shared__ int scnt[Ee];
    int tid = threadIdx.x;
    if (tid < Ee) scnt[tid] = 0;
    __syncthreads();
    for (int bk = tid; bk < Bb * Kk; bk += 256) {
        int e = g_topk_i[bk];
        int slot = atomicAdd(&scnt[e], 1);
        g_glist[e * 256 + slot] = bk;
    }
    __syncthreads();
    if (tid < Ee) g_cnt[tid] = scnt[tid];
}

// ---------------- layer1 via warp tensor cores, fp16 2-segment, cp.async double-buffered ----------------
// grid (4, B*K), 256 threads (8 warps). Block tile 64x64, warp = (mw 0..3, nw 0..1).
// K' segments: seg0 = A_hi*W, seg1 = A_lo*W (W in fp16; A=A_hi+A_lo exact). 16 chunks of k=64.
__global__ void layer1_mma_kernel(const float* __restrict__ b1) {
    __shared__ __half As[2][64 * 72];
    __shared__ __half Bs[2][64 * 72];
    __shared__ float tw_s[64];
    __shared__ float red[4 * 68];
    int bk = blockIdx.y;
    int b = bk / Kk;
    int n0blk = blockIdx.x * 64;
    int e = g_topk_i[bk];
    int tid = threadIdx.x;
    int warp = tid >> 5, lane = tid & 31;
    int mw = warp >> 1, nw = warp & 1;

    if (tid < 64) tw_s[tid] = (tid < Tt) ? g_tw[bk * Tt + tid] : 0.0f;

    long aoff = (long)b * (Tt * Cc);
    const __half* Wp = g_w1h + (long)e * (256 * Cc) + (long)n0blk * Cc;
    const __half* Aseg[2] = { g_dhi + aoff, g_dlo + aoff };

    int row0 = tid >> 3, c0 = (tid & 7) * 8;
    int row1 = (256 + tid) >> 3, c1 = c0;

    auto issue = [&](int ch, int buf) {
        int seg = ch >> 3;
        int kb = (ch & 7) * 64;
        const __half* Ap = Aseg[seg];
        const __half* a0 = (row0 < Tt) ? (Ap + row0 * Cc + kb + c0) : Ap;
        const __half* a1 = (row1 < Tt) ? (Ap + row1 * Cc + kb + c1) : Ap;
        cp16(smem_u32(&As[buf][row0 * 72 + c0]), a0, row0 < Tt ? 16 : 0);
        cp16(smem_u32(&Bs[buf][row0 * 72 + c0]), Wp + row0 * Cc + kb + c0, 16);
        cp16(smem_u32(&As[buf][row1 * 72 + c1]), a1, row1 < Tt ? 16 : 0);
        cp16(smem_u32(&Bs[buf][row1 * 72 + c1]), Wp + row1 * Cc + kb + c1, 16);
        cp_commit();
    };

    float acc[4][4] = {};
    issue(0, 0);
    for (int ch = 0; ch < 16; ch++) {
        int cur = ch & 1;
        if (ch < 15) { issue(ch + 1, cur ^ 1); cp_wait<1>(); }
        else { cp_wait<0>(); }
        __syncthreads();
#pragma unroll
        for (int ks = 0; ks < 4; ks++) {
            uint32_t a[4];
            int arow = mw * 16 + (lane & 15);
            int acol = ks * 16 + (lane >> 4) * 8;
            ldm_x4(a, smem_u32(&As[cur][arow * 72 + acol]));
            uint32_t bf[8];
#pragma unroll
            for (int half = 0; half < 2; half++) {
                int nbase = nw * 32 + half * 16;
                int grp = lane >> 3, l8 = lane & 7;
                int nrow = nbase + (grp >> 1) * 8 + l8;
                int kcol = ks * 16 + (grp & 1) * 8;
                ldm_x4(bf + half * 4, smem_u32(&Bs[cur][nrow * 72 + kcol]));
            }
#pragma unroll
            for (int j = 0; j < 4; j++) mma16816(acc[j], a, bf + j * 2);
        }
        __syncthreads();
    }
    int g = lane >> 2, t4 = lane & 3;
    int r0 = mw * 16 + g, r1 = r0 + 8;
    float w0 = tw_s[r0], w1 = tw_s[r1];
#pragma unroll
    for (int j = 0; j < 4; j++) {
        int nc0 = nw * 32 + j * 8 + t4 * 2;
        float bias0 = b1[e * 256 + n0blk + nc0];
        float bias1 = b1[e * 256 + n0blk + nc0 + 1];
        float s0 = w0 * fmaxf(acc[j][0] + bias0, 0.f) + w1 * fmaxf(acc[j][2] + bias0, 0.f);
        float s1 = w0 * fmaxf(acc[j][1] + bias1, 0.f) + w1 * fmaxf(acc[j][3] + bias1, 0.f);
#pragma unroll
        for (int o = 16; o >= 4; o >>= 1) {
            s0 += __shfl_down_sync(0xffffffffu, s0, o);
            s1 += __shfl_down_sync(0xffffffffu, s1, o);
        }
        if (g == 0) {
            red[mw * 68 + nc0] = s0;
            red[mw * 68 + nc0 + 1] = s1;
        }
    }
    __syncthreads();
    if (tid < 64) {
        float p = red[tid] + red[68 + tid] + red[136 + tid] + red[204 + tid];
        g_pooled[bk * 256 + n0blk + tid] = p;
    }
}

// ---------------- layer2: expert-grouped GEMM ----------------
__global__ void layer2_kernel(const float* __restrict__ w2,
                              const float* __restrict__ b2) {
    int nt = blockIdx.x, mt = blockIdx.y, e = blockIdx.z;
    int cnt = g_cnt[e];
    if (mt * 32 >= cnt) return;
    __shared__ float P[32 * 260];
    __shared__ float Ws[64 * 65];
    __shared__ int prs[32];
    int tid = threadIdx.x;
    int rows = cnt - mt * 32; if (rows > 32) rows = 32;
    if (tid < 32) prs[tid] = (tid < rows) ? g_glist[e * 256 + mt * 32 + tid] : -1;
    __syncthreads();
#pragma unroll
    for (int r = 0; r < 8; r++) {
        int fi = r * 256 + tid;
        int row = fi >> 6, c4 = (fi & 63) * 4;
        float4 v = make_float4(0.f, 0.f, 0.f, 0.f);
        int p = prs[row];
        if (p >= 0) v = *(const float4*)&g_pooled[p * 256 + c4];
        *(float4*)&P[row * 260 + c4] = v;
    }
    int nn = tid & 31, mg = tid >> 5;
    float acc[4][2] = {};
    for (int q = 0; q < 4; q++) {
        __syncthreads();
#pragma unroll
        for (int r = 0; r < 16; r++) {
            int fi = r * 256 + tid;
            int n = fi >> 6, kc = fi & 63;
            Ws[n * 65 + kc] = w2[(e * 512 + nt * 64 + n) * 256 + q * 64 + kc];
        }
        __syncthreads();
#pragma unroll 4
        for (int kc = 0; kc < 64; kc++) {
            float w0 = Ws[nn * 65 + kc];
            float w1 = Ws[(nn + 32) * 65 + kc];
#pragma unroll
            for (int mi = 0; mi < 4; mi++) {
                float pv = P[(mg + mi * 8) * 260 + q * 64 + kc];
                acc[mi][0] += pv * w0;
                acc[mi][1] += pv * w1;
            }
        }
    }
#pragma unroll
    for (int mi = 0; mi < 4; mi++) {
        int row = mg + mi * 8;
        int p = prs[row];
        if (p >= 0) {
            float sw = g_sw[p];
            int cc0 = nt * 64 + nn, cc1 = cc0 + 32;
            g_perexp[p * 512 + cc0] = acc[mi][0] + sw * b2[e * 512 + cc0];
            g_perexp[p * 512 + cc1] = acc[mi][1] + sw * b2[e * 512 + cc1];
        }
    }
}

// ---------------- combine + LayerNorm ----------------
__global__ void ln_kernel(const float* __restrict__ ln_g,
                          const float* __restrict__ ln_b,
                          float* __restrict__ out) {
    int b = blockIdx.x, tid = threadIdx.x;
    __shared__ float red[18];
    float y0 = 0.f, y1 = 0.f;
#pragma unroll
    for (int kk = 0; kk < Kk; kk++) {
        float p = g_topk_p[b * Kk + kk];
        const float* pe = g_perexp + (b * Kk + kk) * 512;
        y0 += p * pe[tid];
        y1 += p * pe[tid + 256];
    }
    float s = y0 + y1, sq = y0 * y0 + y1 * y1;
    int w = tid >> 5, lane = tid & 31;
#pragma unroll
    for (int o = 16; o > 0; o >>= 1) {
        s += __shfl_down_sync(0xffffffffu, s, o);
        sq += __shfl_down_sync(0xffffffffu, sq, o);
    }
    if (lane == 0) { red[w] = s; red[8 + w] = sq; }
    __syncthreads();
    if (tid == 0) {
        float S = 0.f, SQ = 0.f;
        for (int i = 0; i < 8; i++) { S += red[i]; SQ += red[8 + i]; }
        red[16] = S; red[17] = SQ;
    }
    __syncthreads();
    float mean = red[16] * (1.0f / 512.0f);
    float var = red[17] * (1.0f / 512.0f) - mean * mean;
    float rstd = rsqrtf(var + 1e-5f);
    out[b * Cc + tid] = (y0 - mean) * rstd * ln_g[tid] + ln_b[tid];
    out[b * Cc + tid + 256] = (y1 - mean) * rstd * ln_g[tid + 256] + ln_b[tid + 256];
}

// ---------------- launch ----------------
extern "C" void kernel_launch(void* const* d_in, const int* in_sizes, int n_in,
                              void* d_out, int out_size) {
    const float* qst = (const float*)d_in[0];
    const float* data = (const float*)d_in[1];
    const float* ipw = (const float*)d_in[2];
    const float* ipb = (const float*)d_in[3];
    const float* opw = (const float*)d_in[4];
    const float* opb = (const float*)d_in[5];
    const float* rw  = (const float*)d_in[6];
    const float* rb  = (const float*)d_in[7];
    const float* bw  = (const float*)d_in[8];
    const float* bb  = (const float*)d_in[9];
    const float* w1  = (const float*)d_in[10];
    const float* b1  = (const float*)d_in[11];
    const float* w2  = (const float*)d_in[12];
    const float* b2  = (const float*)d_in[13];
    const float* lng = (const float*)d_in[14];
    const float* lnb = (const float*)d_in[15];
    float* out = (float*)d_out;

    split_data_kernel<<<(Bb * Tt * Cc + 255) / 256, 256>>>(data);
    split_w1_kernel<<<(Ee * 256 * Cc + 255) / 256, 256>>>(w1);
    proj_q_kernel<<<dim3(8, 8), 256>>>(qst, ipw, ipb);
    rk_kernel<<<dim3(8, 4, 8), 256>>>(ipw);
    attn_kernel<<<Bb, 256>>>(data, ipb);
    ctx_kernel<<<dim3(8, 8), 256>>>(ipw, ipb);
    proj_tmp_kernel<<<dim3(8, 8), 256>>>(opw, opb);
    router_kernel<<<Bb, 256>>>(rw, rb, bw, bb);
    build_groups_kernel<<<1, 256>>>();
    layer1_mma_kernel<<<dim3(4, Bb * Kk), 256>>>(b1);
    layer2_kernel<<<dim3(8, 8, Ee), 256>>>(w2, b2);
    ln_kernel<<<Bb, 256>>>(lng, lnb, out);
}

// round 9
// speedup vs baseline: 3.4721x; 1.4303x over previous
#include <cuda_runtime.h>
#include <cuda_fp16.h>
#include <cstdint>
#include <math.h>

#define Bb 256
#define Tt 60
#define Cc 512
#define Ee 10
#define Kk 5
#define Hh 8
#define DH 64

// ---------------- scratch (device globals) ----------------
__device__ float g_q[Bb * Cc];
__device__ float g_rk[Bb * Hh * Cc];
__device__ float g_ctx[Bb * Cc];
__device__ float g_tmp[Bb * Cc];
__device__ int   g_topk_i[Bb * Kk];
__device__ float g_topk_p[Bb * Kk];
__device__ float g_tw[Bb * Kk * Tt];
__device__ float g_sw[Bb * Kk];
__device__ float g_pooled[Bb * Kk * 256];
__device__ float g_pd[Bb * Hh * Cc];
__device__ float g_perexp[Bb * Kk * Cc];
__device__ int   g_glist[Ee * 256];
__device__ int   g_cnt[Ee];
// fp16 operands for layer1 tensor-core GEMM (single term each)
__device__ __half g_dh[Bb * Tt * Cc];
__device__ __half g_w1h[Ee * 256 * Cc];

// ---------------- helpers ----------------
__device__ __forceinline__ float softplus_f(float x) {
    return fmaxf(x, 0.0f) + log1pf(expf(-fabsf(x)));
}
__device__ __forceinline__ uint32_t smem_u32(const void* p) {
    return (uint32_t)__cvta_generic_to_shared(p);
}
__device__ __forceinline__ void ldm_x4(uint32_t* r, uint32_t addr) {
    asm volatile("ldmatrix.sync.aligned.m8n8.x4.shared.b16 {%0,%1,%2,%3}, [%4];"
                 : "=r"(r[0]), "=r"(r[1]), "=r"(r[2]), "=r"(r[3]) : "r"(addr));
}
__device__ __forceinline__ void mma16816(float* c, const uint32_t* a, const uint32_t* b) {
    asm volatile(
        "mma.sync.aligned.m16n8k16.row.col.f32.f16.f16.f32 "
        "{%0,%1,%2,%3}, {%4,%5,%6,%7}, {%8,%9}, {%0,%1,%2,%3};"
        : "+f"(c[0]), "+f"(c[1]), "+f"(c[2]), "+f"(c[3])
        : "r"(a[0]), "r"(a[1]), "r"(a[2]), "r"(a[3]), "r"(b[0]), "r"(b[1]));
}
__device__ __forceinline__ void cp16(uint32_t dst, const void* src, int srcsize) {
    asm volatile("cp.async.cg.shared.global [%0], [%1], 16, %2;\n"
                 :: "r"(dst), "l"(src), "r"(srcsize));
}
__device__ __forceinline__ void cp_commit() {
    asm volatile("cp.async.commit_group;\n");
}
template <int N>
__device__ __forceinline__ void cp_wait() {
    asm volatile("cp.async.wait_group %0;\n" :: "n"(N));
}

// ---------------- fp32 -> fp16 conversions ----------------
__global__ void split_data_kernel(const float* __restrict__ x) {
    int i = blockIdx.x * 256 + threadIdx.x;
    if (i < Bb * Tt * Cc) g_dh[i] = __float2half_rn(x[i]);
}
__global__ void split_w1_kernel(const float* __restrict__ x) {
    int i = blockIdx.x * 256 + threadIdx.x;
    if (i < Ee * 256 * Cc) g_w1h[i] = __float2half_rn(x[i]);
}

// ---------------- generic 32x64 SGEMM, double-buffered, k-step 32 ----------------
__device__ __forceinline__ void sgemm_body32(const float* __restrict__ A, int lda,
                                             const float* __restrict__ W,
                                             const float* __restrict__ bias,
                                             float* __restrict__ C, int ldc,
                                             float alpha, int n0, int m0) {
    __shared__ float As[2][32 * 36];   // [kc][m], pitch 36
    __shared__ float Ws[2][32 * 68];   // [kc][n], pitch 68
    int tid = threadIdx.x;
    int ty = tid >> 4, tx = tid & 15;
    float acc[2][4] = {};
    float ar[4], wr[8];
#pragma unroll
    for (int r = 0; r < 4; r++) { int l = r * 256 + tid; int m = l >> 5, kc = l & 31; ar[r] = A[(m0 + m) * lda + kc]; }
#pragma unroll
    for (int r = 0; r < 8; r++) { int l = r * 256 + tid; int n = l >> 5, kc = l & 31; wr[r] = W[(n0 + n) * 512 + kc]; }
#pragma unroll
    for (int r = 0; r < 4; r++) { int l = r * 256 + tid; int m = l >> 5, kc = l & 31; As[0][kc * 36 + m] = ar[r]; }
#pragma unroll
    for (int r = 0; r < 8; r++) { int l = r * 256 + tid; int n = l >> 5, kc = l & 31; Ws[0][kc * 68 + n] = wr[r]; }
    for (int i = 0; i < 16; i++) {
        int cur = i & 1;
        if (i < 15) {
            int k0 = (i + 1) * 32;
#pragma unroll
            for (int r = 0; r < 4; r++) { int l = r * 256 + tid; int m = l >> 5, kc = l & 31; ar[r] = A[(m0 + m) * lda + k0 + kc]; }
#pragma unroll
            for (int r = 0; r < 8; r++) { int l = r * 256 + tid; int n = l >> 5, kc = l & 31; wr[r] = W[(n0 + n) * 512 + k0 + kc]; }
        }
        __syncthreads();
#pragma unroll
        for (int kc = 0; kc < 32; kc++) {
            float a0 = As[cur][kc * 36 + ty * 2];
            float a1 = As[cur][kc * 36 + ty * 2 + 1];
            float4 bv = *(const float4*)&Ws[cur][kc * 68 + tx * 4];
            acc[0][0] += a0 * bv.x; acc[0][1] += a0 * bv.y;
            acc[0][2] += a0 * bv.z; acc[0][3] += a0 * bv.w;
            acc[1][0] += a1 * bv.x; acc[1][1] += a1 * bv.y;
            acc[1][2] += a1 * bv.z; acc[1][3] += a1 * bv.w;
        }
        if (i < 15) {
            int nb = cur ^ 1;
#pragma unroll
            for (int r = 0; r < 4; r++) { int l = r * 256 + tid; int m = l >> 5, kc = l & 31; As[nb][kc * 36 + m] = ar[r]; }
#pragma unroll
            for (int r = 0; r < 8; r++) { int l = r * 256 + tid; int n = l >> 5, kc = l & 31; Ws[nb][kc * 68 + n] = wr[r]; }
        }
    }
#pragma unroll
    for (int i = 0; i < 2; i++) {
        int m = m0 + ty * 2 + i;
#pragma unroll
        for (int j = 0; j < 4; j++) {
            int n = n0 + tx * 4 + j;
            C[m * ldc + n] = alpha * (acc[i][j] + bias[n]);
        }
    }
}
__global__ void proj_q_kernel(const float* __restrict__ qst,
                              const float* __restrict__ ipw,
                              const float* __restrict__ ipb) {
    sgemm_body32(qst, 512, ipw, ipb, g_q, 512, 0.125f, blockIdx.x * 64, blockIdx.y * 32);
}
__global__ void proj_tmp_kernel(const float* __restrict__ opw,
                                const float* __restrict__ opb) {
    sgemm_body32(g_ctx, 512, opw, opb, g_tmp, 512, 1.0f, blockIdx.x * 64, blockIdx.y * 32);
}
__global__ void ctx_kernel(const float* __restrict__ ipw,
                           const float* __restrict__ ipb) {
    int h = blockIdx.x;
    sgemm_body32(g_pd + h * 512, Hh * 512,
                 ipw + (1024 + h * 64) * 512,
                 ipb + 1024 + h * 64,
                 g_ctx + h * 64, 512, 1.0f, 0, blockIdx.y * 32);
}

// ---------------- rk = q_h @ Wk_h : 8 GEMMs of [256 x 512 x 64] ----------------
__global__ void rk_kernel(const float* __restrict__ ipw) {
    __shared__ float As[16 * 68];
    __shared__ float Ws[16 * 68];
    int n0 = blockIdx.x * 64, m0 = blockIdx.y * 64, h = blockIdx.z;
    int tid = threadIdx.x, ty = tid >> 4, tx = tid & 15;
    float acc[4][4] = {};
    for (int kk = 0; kk < 64; kk += 16) {
#pragma unroll
        for (int r = 0; r < 4; r++) {
            int l = r * 256 + tid;
            int m = l >> 4, kc = l & 15;
            As[kc * 68 + m] = g_q[(m0 + m) * 512 + h * 64 + kk + kc];
        }
#pragma unroll
        for (int r = 0; r < 4; r++) {
            int l = r * 256 + tid;
            int kc = l >> 6, n = l & 63;
            Ws[kc * 68 + n] = ipw[(512 + h * 64 + kk + kc) * 512 + n0 + n];
        }
        __syncthreads();
#pragma unroll
        for (int kc = 0; kc < 16; kc++) {
            float4 av = *(const float4*)&As[kc * 68 + ty * 4];
            float4 bv = *(const float4*)&Ws[kc * 68 + tx * 4];
            float a[4] = {av.x, av.y, av.z, av.w};
            float b[4] = {bv.x, bv.y, bv.z, bv.w};
#pragma unroll
            for (int i = 0; i < 4; i++)
#pragma unroll
                for (int j = 0; j < 4; j++) acc[i][j] += a[i] * b[j];
        }
        __syncthreads();
    }
#pragma unroll
    for (int i = 0; i < 4; i++) {
        int b = m0 + ty * 4 + i;
#pragma unroll
        for (int j = 0; j < 4; j++)
            g_rk[(b * Hh + h) * 512 + n0 + tx * 4 + j] = acc[i][j];
    }
}

// ---------------- attention per b ----------------
__global__ void attn_kernel(const float* __restrict__ data,
                            const float* __restrict__ ipb) {
    int b = blockIdx.x, tid = threadIdx.x;
    __shared__ float rks[8 * 512];
    __shared__ float scr[8][64];
    __shared__ float qb_s[8];
    const float* rkg = g_rk + b * (Hh * 512);
    for (int i = tid * 4; i < 4096; i += 1024)
        *(float4*)&rks[i] = *(const float4*)&rkg[i];
    if (tid < 32) scr[tid >> 2][60 + (tid & 3)] = -1e30f;
    int w = tid >> 5, lane = tid & 31;
    {
        float s = g_q[b * 512 + w * 64 + lane] * ipb[512 + w * 64 + lane]
                + g_q[b * 512 + w * 64 + 32 + lane] * ipb[512 + w * 64 + 32 + lane];
#pragma unroll
        for (int o = 16; o > 0; o >>= 1) s += __shfl_down_sync(0xffffffffu, s, o);
        if (lane == 0) qb_s[w] = s;
    }
    __syncthreads();
    for (int t = w; t < Tt; t += 8) {
        const float* dp = data + (b * Tt + t) * 512;
        float part[8] = {};
#pragma unroll
        for (int j = 0; j < 4; j++) {
            float4 d4 = *(const float4*)&dp[j * 128 + lane * 4];
#pragma unroll
            for (int h = 0; h < 8; h++) {
                float4 r4 = *(const float4*)&rks[h * 512 + j * 128 + lane * 4];
                part[h] += d4.x * r4.x + d4.y * r4.y + d4.z * r4.z + d4.w * r4.w;
            }
        }
#pragma unroll
        for (int h = 0; h < 8; h++) {
            float s = part[h];
#pragma unroll
            for (int o = 16; o > 0; o >>= 1) s += __shfl_down_sync(0xffffffffu, s, o);
            if (lane == 0) scr[h][t] = s + qb_s[h];
        }
    }
    __syncthreads();
    {
        float v0 = scr[w][lane];
        float v1 = scr[w][lane + 32];
        float m = fmaxf(v0, v1);
#pragma unroll
        for (int o = 16; o > 0; o >>= 1) m = fmaxf(m, __shfl_xor_sync(0xffffffffu, m, o));
        float e0 = (lane < Tt) ? expf(v0 - m) : 0.0f;
        float e1 = (lane + 32 < Tt) ? expf(v1 - m) : 0.0f;
        float s = e0 + e1;
#pragma unroll
        for (int o = 16; o > 0; o >>= 1) s += __shfl_xor_sync(0xffffffffu, s, o);
        float inv = 1.0f / s;
        scr[w][lane] = e0 * inv;
        scr[w][lane + 32] = e1 * inv;
    }
    __syncthreads();
    float acc[8][2] = {};
    const float* dpb = data + b * Tt * 512;
    for (int t = 0; t < Tt; t++) {
        float d0 = dpb[t * 512 + tid];
        float d1 = dpb[t * 512 + tid + 256];
#pragma unroll
        for (int h = 0; h < 8; h++) {
            float p = scr[h][t];
            acc[h][0] += p * d0;
            acc[h][1] += p * d1;
        }
    }
#pragma unroll
    for (int h = 0; h < 8; h++) {
        g_pd[(b * Hh + h) * 512 + tid] = acc[h][0];
        g_pd[(b * Hh + h) * 512 + tid + 256] = acc[h][1];
    }
}

// ---------------- router + top-k + beta time weights ----------------
__global__ void router_kernel(const float* __restrict__ router_w,
                              const float* __restrict__ router_b,
                              const float* __restrict__ beta_w,
                              const float* __restrict__ beta_b) {
    int b = blockIdx.x;
    __shared__ float tmp_s[512];
    __shared__ float logit[32];
    __shared__ float al[Ee], be[Ee];
    __shared__ int sel_i[Kk];
    __shared__ float w_s[Kk * Tt];
    int tid = threadIdx.x;
    for (int c = tid; c < 512; c += 256) tmp_s[c] = g_tmp[b * Cc + c];
    __syncthreads();
    int w = tid >> 5, lane = tid & 31;
    for (int r = w; r < 30; r += 8) {
        const float* wr; float bias;
        if (r < Ee) { wr = router_w + r * 512; bias = router_b[r]; }
        else { wr = beta_w + (r - Ee) * 512; bias = beta_b[r - Ee]; }
        float s = 0.f;
        for (int c = lane; c < 512; c += 32) s += wr[c] * tmp_s[c];
#pragma unroll
        for (int o = 16; o > 0; o >>= 1) s += __shfl_down_sync(0xffffffffu, s, o);
        if (lane == 0) logit[r] = s + bias;
    }
    __syncthreads();
    if (tid < Ee) {
        al[tid] = softplus_f(logit[Ee + 2 * tid]) + 1e-6f;
        be[tid] = softplus_f(logit[Ee + 2 * tid + 1]) + 1e-6f;
    }
    if (tid == 0) {
        float m = logit[0];
        for (int e = 1; e < Ee; e++) m = fmaxf(m, logit[e]);
        float pe[Ee]; float s = 0.f;
        for (int e = 0; e < Ee; e++) { pe[e] = expf(logit[e] - m); s += pe[e]; }
        float invs = 1.0f / s;
        for (int e = 0; e < Ee; e++) pe[e] *= invs;
        bool used[Ee] = {};
        float psum = 0.f; float sp[Kk];
        for (int kk = 0; kk < Kk; kk++) {
            int best = 0; float bv = -1.f;
            for (int e = 0; e < Ee; e++)
                if (!used[e] && pe[e] > bv) { bv = pe[e]; best = e; }
            used[best] = true; sel_i[kk] = best; sp[kk] = bv; psum += bv;
        }
        float inv = 1.0f / (psum + 1e-8f);
        for (int kk = 0; kk < Kk; kk++) {
            g_topk_i[b * Kk + kk] = sel_i[kk];
            g_topk_p[b * Kk + kk] = sp[kk] * inv;
        }
    }
    __syncthreads();
    for (int i = tid; i < Kk * Tt; i += 256) {
        int kk = i / Tt, t = i % Tt;
        int e = sel_i[kk];
        float a = al[e], bb = be[e];
        float tt = (float)t / 59.0f;
        float lt = logf(tt + 1e-12f);
        float l1 = logf(1.0f - tt + 1e-12f);
        float norm = lgammaf(a) + lgammaf(bb) - lgammaf(a + bb);
        w_s[i] = expf((a - 1.0f) * lt + (bb - 1.0f) * l1 - norm);
    }
    __syncthreads();
    if (tid < Kk) {
        float m = 0.f;
        for (int t = 0; t < Tt; t++) m = fmaxf(m, w_s[tid * Tt + t]);
        float inv = 1.0f / (m + 1e-8f);
        float s = 0.f;
        for (int t = 0; t < Tt; t++) {
            float v = w_s[tid * Tt + t] * inv;
            g_tw[(b * Kk + tid) * Tt + t] = v;
            s += v;
        }
        g_sw[b * Kk + tid] = s;
    }
}

// ---------------- build per-expert pair lists ----------------
__global__ void build_groups_kernel() {
    __shared__ int scnt[Ee];
    int tid = threadIdx.x;
    if (tid < Ee) scnt[tid] = 0;
    __syncthreads();
    for (int bk = tid; bk < Bb * Kk; bk += 256) {
        int e = g_topk_i[bk];
        int slot = atomicAdd(&scnt[e], 1);
        g_glist[e * 256 + slot] = bk;
    }
    __syncthreads();
    if (tid < Ee) g_cnt[tid] = scnt[tid];
}

// ---------------- layer1 via warp tensor cores, fp16 single-seg, cp.async double-buffered ----------------
// grid (4, B*K), 256 threads (8 warps). Block tile 64x64, warp = (mw 0..3, nw 0..1).
// K = 512 in 8 chunks of 64.
__global__ void layer1_mma_kernel(const float* __restrict__ b1) {
    __shared__ __half As[2][64 * 72];
    __shared__ __half Bs[2][64 * 72];
    __shared__ float tw_s[64];
    __shared__ float red[4 * 68];
    int bk = blockIdx.y;
    int b = bk / Kk;
    int n0blk = blockIdx.x * 64;
    int e = g_topk_i[bk];
    int tid = threadIdx.x;
    int warp = tid >> 5, lane = tid & 31;
    int mw = warp >> 1, nw = warp & 1;

    if (tid < 64) tw_s[tid] = (tid < Tt) ? g_tw[bk * Tt + tid] : 0.0f;

    const __half* Ap = g_dh + (long)b * (Tt * Cc);
    const __half* Wp = g_w1h + (long)e * (256 * Cc) + (long)n0blk * Cc;

    int row0 = tid >> 3, c0 = (tid & 7) * 8;
    int row1 = (256 + tid) >> 3, c1 = c0;

    auto issue = [&](int ch, int buf) {
        int kb = ch * 64;
        const __half* a0 = (row0 < Tt) ? (Ap + row0 * Cc + kb + c0) : Ap;
        const __half* a1 = (row1 < Tt) ? (Ap + row1 * Cc + kb + c1) : Ap;
        cp16(smem_u32(&As[buf][row0 * 72 + c0]), a0, row0 < Tt ? 16 : 0);
        cp16(smem_u32(&Bs[buf][row0 * 72 + c0]), Wp + row0 * Cc + kb + c0, 16);
        cp16(smem_u32(&As[buf][row1 * 72 + c1]), a1, row1 < Tt ? 16 : 0);
        cp16(smem_u32(&Bs[buf][row1 * 72 + c1]), Wp + row1 * Cc + kb + c1, 16);
        cp_commit();
    };

    float acc[4][4] = {};
    issue(0, 0);
    for (int ch = 0; ch < 8; ch++) {
        int cur = ch & 1;
        if (ch < 7) { issue(ch + 1, cur ^ 1); cp_wait<1>(); }
        else { cp_wait<0>(); }
        __syncthreads();
#pragma unroll
        for (int ks = 0; ks < 4; ks++) {
            uint32_t a[4];
            int arow = mw * 16 + (lane & 15);
            int acol = ks * 16 + (lane >> 4) * 8;
            ldm_x4(a, smem_u32(&As[cur][arow * 72 + acol]));
            uint32_t bf[8];
#pragma unroll
            for (int half = 0; half < 2; half++) {
                int nbase = nw * 32 + half * 16;
                int grp = lane >> 3, l8 = lane & 7;
                int nrow = nbase + (grp >> 1) * 8 + l8;
                int kcol = ks * 16 + (grp & 1) * 8;
                ldm_x4(bf + half * 4, smem_u32(&Bs[cur][nrow * 72 + kcol]));
            }
#pragma unroll
            for (int j = 0; j < 4; j++) mma16816(acc[j], a, bf + j * 2);
        }
        __syncthreads();
    }
    int g = lane >> 2, t4 = lane & 3;
    int r0 = mw * 16 + g, r1 = r0 + 8;
    float w0 = tw_s[r0], w1 = tw_s[r1];
#pragma unroll
    for (int j = 0; j < 4; j++) {
        int nc0 = nw * 32 + j * 8 + t4 * 2;
        float bias0 = b1[e * 256 + n0blk + nc0];
        float bias1 = b1[e * 256 + n0blk + nc0 + 1];
        float s0 = w0 * fmaxf(acc[j][0] + bias0, 0.f) + w1 * fmaxf(acc[j][2] + bias0, 0.f);
        float s1 = w0 * fmaxf(acc[j][1] + bias1, 0.f) + w1 * fmaxf(acc[j][3] + bias1, 0.f);
#pragma unroll
        for (int o = 16; o >= 4; o >>= 1) {
            s0 += __shfl_down_sync(0xffffffffu, s0, o);
            s1 += __shfl_down_sync(0xffffffffu, s1, o);
        }
        if (g == 0) {
            red[mw * 68 + nc0] = s0;
            red[mw * 68 + nc0 + 1] = s1;
        }
    }
    __syncthreads();
    if (tid < 64) {
        float p = red[tid] + red[68 + tid] + red[136 + tid] + red[204 + tid];
        g_pooled[bk * 256 + n0blk + tid] = p;
    }
}

// ---------------- layer2: expert-grouped GEMM ----------------
__global__ void layer2_kernel(const float* __restrict__ w2,
                              const float* __restrict__ b2) {
    int nt = blockIdx.x, mt = blockIdx.y, e = blockIdx.z;
    int cnt = g_cnt[e];
    if (mt * 32 >= cnt) return;
    __shared__ float P[32 * 260];
    __shared__ float Ws[64 * 65];
    __shared__ int prs[32];
    int tid = threadIdx.x;
    int rows = cnt - mt * 32; if (rows > 32) rows = 32;
    if (tid < 32) prs[tid] = (tid < rows) ? g_glist[e * 256 + mt * 32 + tid] : -1;
    __syncthreads();
#pragma unroll
    for (int r = 0; r < 8; r++) {
        int fi = r * 256 + tid;
        int row = fi >> 6, c4 = (fi & 63) * 4;
        float4 v = make_float4(0.f, 0.f, 0.f, 0.f);
        int p = prs[row];
        if (p >= 0) v = *(const float4*)&g_pooled[p * 256 + c4];
        *(float4*)&P[row * 260 + c4] = v;
    }
    int nn = tid & 31, mg = tid >> 5;
    float acc[4][2] = {};
    for (int q = 0; q < 4; q++) {
        __syncthreads();
#pragma unroll
        for (int r = 0; r < 16; r++) {
            int fi = r * 256 + tid;
            int n = fi >> 6, kc = fi & 63;
            Ws[n * 65 + kc] = w2[(e * 512 + nt * 64 + n) * 256 + q * 64 + kc];
        }
        __syncthreads();
#pragma unroll 4
        for (int kc = 0; kc < 64; kc++) {
            float w0 = Ws[nn * 65 + kc];
            float w1 = Ws[(nn + 32) * 65 + kc];
#pragma unroll
            for (int mi = 0; mi < 4; mi++) {
                float pv = P[(mg + mi * 8) * 260 + q * 64 + kc];
                acc[mi][0] += pv * w0;
                acc[mi][1] += pv * w1;
            }
        }
    }
#pragma unroll
    for (int mi = 0; mi < 4; mi++) {
        int row = mg + mi * 8;
        int p = prs[row];
        if (p >= 0) {
            float sw = g_sw[p];
            int cc0 = nt * 64 + nn, cc1 = cc0 + 32;
            g_perexp[p * 512 + cc0] = acc[mi][0] + sw * b2[e * 512 + cc0];
            g_perexp[p * 512 + cc1] = acc[mi][1] + sw * b2[e * 512 + cc1];
        }
    }
}

// ---------------- combine + LayerNorm ----------------
__global__ void ln_kernel(const float* __restrict__ ln_g,
                          const float* __restrict__ ln_b,
                          float* __restrict__ out) {
    int b = blockIdx.x, tid = threadIdx.x;
    __shared__ float red[18];
    float y0 = 0.f, y1 = 0.f;
#pragma unroll
    for (int kk = 0; kk < Kk; kk++) {
        float p = g_topk_p[b * Kk + kk];
        const float* pe = g_perexp + (b * Kk + kk) * 512;
        y0 += p * pe[tid];
        y1 += p * pe[tid + 256];
    }
    float s = y0 + y1, sq = y0 * y0 + y1 * y1;
    int w = tid >> 5, lane = tid & 31;
#pragma unroll
    for (int o = 16; o > 0; o >>= 1) {
        s += __shfl_down_sync(0xffffffffu, s, o);
        sq += __shfl_down_sync(0xffffffffu, sq, o);
    }
    if (lane == 0) { red[w] = s; red[8 + w] = sq; }
    __syncthreads();
    if (tid == 0) {
        float S = 0.f, SQ = 0.f;
        for (int i = 0; i < 8; i++) { S += red[i]; SQ += red[8 + i]; }
        red[16] = S; red[17] = SQ;
    }
    __syncthreads();
    float mean = red[16] * (1.0f / 512.0f);
    float var = red[17] * (1.0f / 512.0f) - mean * mean;
    float rstd = rsqrtf(var + 1e-5f);
    out[b * Cc + tid] = (y0 - mean) * rstd * ln_g[tid] + ln_b[tid];
    out[b * Cc + tid + 256] = (y1 - mean) * rstd * ln_g[tid + 256] + ln_b[tid + 256];
}

// ---------------- launch ----------------
extern "C" void kernel_launch(void* const* d_in, const int* in_sizes, int n_in,
                              void* d_out, int out_size) {
    const float* qst = (const float*)d_in[0];
    const float* data = (const float*)d_in[1];
    const float* ipw = (const float*)d_in[2];
    const float* ipb = (const float*)d_in[3];
    const float* opw = (const float*)d_in[4];
    const float* opb = (const float*)d_in[5];
    const float* rw  = (const float*)d_in[6];
    const float* rb  = (const float*)d_in[7];
    const float* bw  = (const float*)d_in[8];
    const float* bb  = (const float*)d_in[9];
    const float* w1  = (const float*)d_in[10];
    const float* b1  = (const float*)d_in[11];
    const float* w2  = (const float*)d_in[12];
    const float* b2  = (const float*)d_in[13];
    const float* lng = (const float*)d_in[14];
    const float* lnb = (const float*)d_in[15];
    float* out = (float*)d_out;

    split_data_kernel<<<(Bb * Tt * Cc + 255) / 256, 256>>>(data);
    split_w1_kernel<<<(Ee * 256 * Cc + 255) / 256, 256>>>(w1);
    proj_q_kernel<<<dim3(8, 8), 256>>>(qst, ipw, ipb);
    rk_kernel<<<dim3(8, 4, 8), 256>>>(ipw);
    attn_kernel<<<Bb, 256>>>(data, ipb);
    ctx_kernel<<<dim3(8, 8), 256>>>(ipw, ipb);
    proj_tmp_kernel<<<dim3(8, 8), 256>>>(opw, opb);
    router_kernel<<<Bb, 256>>>(rw, rb, bw, bb);
    build_groups_kernel<<<1, 256>>>();
    layer1_mma_kernel<<<dim3(4, Bb * Kk), 256>>>(b1);
    layer2_kernel<<<dim3(8, 8, Ee), 256>>>(w2, b2);
    ln_kernel<<<Bb, 256>>>(lng, lnb, out);
}

// round 10
// speedup vs baseline: 3.7287x; 1.0739x over previous
#include <cuda_runtime.h>
#include <cuda_fp16.h>
#include <cstdint>
#include <math.h>

#define Bb 256
#define Tt 60
#define Cc 512
#define Ee 10
#define Kk 5
#define Hh 8
#define DH 64

// ---------------- scratch (device globals) ----------------
__device__ float g_q[Bb * Cc];
__device__ float g_rk[Bb * Hh * Cc];
__device__ float g_ctx[Bb * Cc];
__device__ float g_tmp[Bb * Cc];
__device__ int   g_topk_i[Bb * Kk];
__device__ float g_topk_p[Bb * Kk];
__device__ float g_tw[Bb * Kk * Tt];
__device__ float g_sw[Bb * Kk];
__device__ float g_pooled[Bb * Kk * 256];
__device__ float g_pd[Bb * Hh * Cc];
__device__ float g_perexp[Bb * Kk * Cc];
__device__ int   g_glist[Ee * 256];
__device__ int   g_cnt[Ee];
__device__ __half g_dh[Bb * Tt * Cc];
__device__ __half g_w1h[Ee * 256 * Cc];

// ---------------- helpers ----------------
__device__ __forceinline__ float softplus_f(float x) {
    return fmaxf(x, 0.0f) + log1pf(expf(-fabsf(x)));
}
__device__ __forceinline__ uint32_t smem_u32(const void* p) {
    return (uint32_t)__cvta_generic_to_shared(p);
}
__device__ __forceinline__ void ldm_x4(uint32_t* r, uint32_t addr) {
    asm volatile("ldmatrix.sync.aligned.m8n8.x4.shared.b16 {%0,%1,%2,%3}, [%4];"
                 : "=r"(r[0]), "=r"(r[1]), "=r"(r[2]), "=r"(r[3]) : "r"(addr));
}
__device__ __forceinline__ void mma16816(float* c, const uint32_t* a, const uint32_t* b) {
    asm volatile(
        "mma.sync.aligned.m16n8k16.row.col.f32.f16.f16.f32 "
        "{%0,%1,%2,%3}, {%4,%5,%6,%7}, {%8,%9}, {%0,%1,%2,%3};"
        : "+f"(c[0]), "+f"(c[1]), "+f"(c[2]), "+f"(c[3])
        : "r"(a[0]), "r"(a[1]), "r"(a[2]), "r"(a[3]), "r"(b[0]), "r"(b[1]));
}
__device__ __forceinline__ void cp16(uint32_t dst, const void* src, int srcsize) {
    asm volatile("cp.async.cg.shared.global [%0], [%1], 16, %2;\n"
                 :: "r"(dst), "l"(src), "r"(srcsize));
}
__device__ __forceinline__ void cp_commit() {
    asm volatile("cp.async.commit_group;\n");
}
template <int N>
__device__ __forceinline__ void cp_wait() {
    asm volatile("cp.async.wait_group %0;\n" :: "n"(N));
}

// ---------------- prep: fp16 conversions + g_cnt zeroing (one launch) ----------------
__global__ void prep_kernel(const float* __restrict__ data, const float* __restrict__ w1) {
    int i = blockIdx.x * 256 + threadIdx.x;
    if (i < Bb * Tt * Cc) g_dh[i] = __float2half_rn(data[i]);
    if (i < Ee * 256 * Cc) g_w1h[i] = __float2half_rn(w1[i]);
    if (i < Ee) g_cnt[i] = 0;
}

// ---------------- generic 32x64 SGEMM, double-buffered, k-step 32 ----------------
__device__ __forceinline__ void sgemm_body32(const float* __restrict__ A, int lda,
                                             const float* __restrict__ W,
                                             const float* __restrict__ bias,
                                             float* __restrict__ C, int ldc,
                                             float alpha, int n0, int m0) {
    __shared__ float As[2][32 * 36];
    __shared__ float Ws[2][32 * 68];
    int tid = threadIdx.x;
    int ty = tid >> 4, tx = tid & 15;
    float acc[2][4] = {};
    float ar[4], wr[8];
#pragma unroll
    for (int r = 0; r < 4; r++) { int l = r * 256 + tid; int m = l >> 5, kc = l & 31; ar[r] = A[(m0 + m) * lda + kc]; }
#pragma unroll
    for (int r = 0; r < 8; r++) { int l = r * 256 + tid; int n = l >> 5, kc = l & 31; wr[r] = W[(n0 + n) * 512 + kc]; }
#pragma unroll
    for (int r = 0; r < 4; r++) { int l = r * 256 + tid; int m = l >> 5, kc = l & 31; As[0][kc * 36 + m] = ar[r]; }
#pragma unroll
    for (int r = 0; r < 8; r++) { int l = r * 256 + tid; int n = l >> 5, kc = l & 31; Ws[0][kc * 68 + n] = wr[r]; }
    for (int i = 0; i < 16; i++) {
        int cur = i & 1;
        if (i < 15) {
            int k0 = (i + 1) * 32;
#pragma unroll
            for (int r = 0; r < 4; r++) { int l = r * 256 + tid; int m = l >> 5, kc = l & 31; ar[r] = A[(m0 + m) * lda + k0 + kc]; }
#pragma unroll
            for (int r = 0; r < 8; r++) { int l = r * 256 + tid; int n = l >> 5, kc = l & 31; wr[r] = W[(n0 + n) * 512 + k0 + kc]; }
        }
        __syncthreads();
#pragma unroll
        for (int kc = 0; kc < 32; kc++) {
            float a0 = As[cur][kc * 36 + ty * 2];
            float a1 = As[cur][kc * 36 + ty * 2 + 1];
            float4 bv = *(const float4*)&Ws[cur][kc * 68 + tx * 4];
            acc[0][0] += a0 * bv.x; acc[0][1] += a0 * bv.y;
            acc[0][2] += a0 * bv.z; acc[0][3] += a0 * bv.w;
            acc[1][0] += a1 * bv.x; acc[1][1] += a1 * bv.y;
            acc[1][2] += a1 * bv.z; acc[1][3] += a1 * bv.w;
        }
        if (i < 15) {
            int nb = cur ^ 1;
#pragma unroll
            for (int r = 0; r < 4; r++) { int l = r * 256 + tid; int m = l >> 5, kc = l & 31; As[nb][kc * 36 + m] = ar[r]; }
#pragma unroll
            for (int r = 0; r < 8; r++) { int l = r * 256 + tid; int n = l >> 5, kc = l & 31; Ws[nb][kc * 68 + n] = wr[r]; }
        }
    }
#pragma unroll
    for (int i = 0; i < 2; i++) {
        int m = m0 + ty * 2 + i;
#pragma unroll
        for (int j = 0; j < 4; j++) {
            int n = n0 + tx * 4 + j;
            C[m * ldc + n] = alpha * (acc[i][j] + bias[n]);
        }
    }
}
__global__ void proj_q_kernel(const float* __restrict__ qst,
                              const float* __restrict__ ipw,
                              const float* __restrict__ ipb) {
    sgemm_body32(qst, 512, ipw, ipb, g_q, 512, 0.125f, blockIdx.x * 64, blockIdx.y * 32);
}
__global__ void proj_tmp_kernel(const float* __restrict__ opw,
                                const float* __restrict__ opb) {
    sgemm_body32(g_ctx, 512, opw, opb, g_tmp, 512, 1.0f, blockIdx.x * 64, blockIdx.y * 32);
}
__global__ void ctx_kernel(const float* __restrict__ ipw,
                           const float* __restrict__ ipb) {
    int h = blockIdx.x;
    sgemm_body32(g_pd + h * 512, Hh * 512,
                 ipw + (1024 + h * 64) * 512,
                 ipb + 1024 + h * 64,
                 g_ctx + h * 64, 512, 1.0f, 0, blockIdx.y * 32);
}

// ---------------- rk = q_h @ Wk_h : 32x64 tiles, grid (8n, 8m, 8h) ----------------
__global__ void rk_kernel(const float* __restrict__ ipw) {
    __shared__ float As[16 * 36];
    __shared__ float Ws[16 * 68];
    int n0 = blockIdx.x * 64, m0 = blockIdx.y * 32, h = blockIdx.z;
    int tid = threadIdx.x, ty = tid >> 4, tx = tid & 15;
    float acc[2][4] = {};
    for (int kk = 0; kk < 64; kk += 16) {
#pragma unroll
        for (int r = 0; r < 2; r++) {
            int l = r * 256 + tid;
            int m = l >> 4, kc = l & 15;
            As[kc * 36 + m] = g_q[(m0 + m) * 512 + h * 64 + kk + kc];
        }
#pragma unroll
        for (int r = 0; r < 4; r++) {
            int l = r * 256 + tid;
            int kc = l >> 6, n = l & 63;
            Ws[kc * 68 + n] = ipw[(512 + h * 64 + kk + kc) * 512 + n0 + n];
        }
        __syncthreads();
#pragma unroll
        for (int kc = 0; kc < 16; kc++) {
            float a0 = As[kc * 36 + ty * 2];
            float a1 = As[kc * 36 + ty * 2 + 1];
            float4 bv = *(const float4*)&Ws[kc * 68 + tx * 4];
            acc[0][0] += a0 * bv.x; acc[0][1] += a0 * bv.y;
            acc[0][2] += a0 * bv.z; acc[0][3] += a0 * bv.w;
            acc[1][0] += a1 * bv.x; acc[1][1] += a1 * bv.y;
            acc[1][2] += a1 * bv.z; acc[1][3] += a1 * bv.w;
        }
        __syncthreads();
    }
#pragma unroll
    for (int i = 0; i < 2; i++) {
        int b = m0 + ty * 2 + i;
#pragma unroll
        for (int j = 0; j < 4; j++)
            g_rk[(b * Hh + h) * 512 + n0 + tx * 4 + j] = acc[i][j];
    }
}

// ---------------- attention per b ----------------
__global__ void attn_kernel(const float* __restrict__ data,
                            const float* __restrict__ ipb) {
    int b = blockIdx.x, tid = threadIdx.x;
    __shared__ float rks[8 * 512];
    __shared__ float scr[8][64];
    __shared__ float qb_s[8];
    const float* rkg = g_rk + b * (Hh * 512);
    for (int i = tid * 4; i < 4096; i += 1024)
        *(float4*)&rks[i] = *(const float4*)&rkg[i];
    if (tid < 32) scr[tid >> 2][60 + (tid & 3)] = -1e30f;
    int w = tid >> 5, lane = tid & 31;
    {
        float s = g_q[b * 512 + w * 64 + lane] * ipb[512 + w * 64 + lane]
                + g_q[b * 512 + w * 64 + 32 + lane] * ipb[512 + w * 64 + 32 + lane];
#pragma unroll
        for (int o = 16; o > 0; o >>= 1) s += __shfl_down_sync(0xffffffffu, s, o);
        if (lane == 0) qb_s[w] = s;
    }
    __syncthreads();
    for (int t = w; t < Tt; t += 8) {
        const float* dp = data + (b * Tt + t) * 512;
        float part[8] = {};
#pragma unroll
        for (int j = 0; j < 4; j++) {
            float4 d4 = *(const float4*)&dp[j * 128 + lane * 4];
#pragma unroll
            for (int h = 0; h < 8; h++) {
                float4 r4 = *(const float4*)&rks[h * 512 + j * 128 + lane * 4];
                part[h] += d4.x * r4.x + d4.y * r4.y + d4.z * r4.z + d4.w * r4.w;
            }
        }
#pragma unroll
        for (int h = 0; h < 8; h++) {
            float s = part[h];
#pragma unroll
            for (int o = 16; o > 0; o >>= 1) s += __shfl_down_sync(0xffffffffu, s, o);
            if (lane == 0) scr[h][t] = s + qb_s[h];
        }
    }
    __syncthreads();
    {
        float v0 = scr[w][lane];
        float v1 = scr[w][lane + 32];
        float m = fmaxf(v0, v1);
#pragma unroll
        for (int o = 16; o > 0; o >>= 1) m = fmaxf(m, __shfl_xor_sync(0xffffffffu, m, o));
        float e0 = (lane < Tt) ? expf(v0 - m) : 0.0f;
        float e1 = (lane + 32 < Tt) ? expf(v1 - m) : 0.0f;
        float s = e0 + e1;
#pragma unroll
        for (int o = 16; o > 0; o >>= 1) s += __shfl_xor_sync(0xffffffffu, s, o);
        float inv = 1.0f / s;
        scr[w][lane] = e0 * inv;
        scr[w][lane + 32] = e1 * inv;
    }
    __syncthreads();
    float acc[8][2] = {};
    const float* dpb = data + b * Tt * 512;
    for (int t = 0; t < Tt; t++) {
        float d0 = dpb[t * 512 + tid];
        float d1 = dpb[t * 512 + tid + 256];
#pragma unroll
        for (int h = 0; h < 8; h++) {
            float p = scr[h][t];
            acc[h][0] += p * d0;
            acc[h][1] += p * d1;
        }
    }
#pragma unroll
    for (int h = 0; h < 8; h++) {
        g_pd[(b * Hh + h) * 512 + tid] = acc[h][0];
        g_pd[(b * Hh + h) * 512 + tid + 256] = acc[h][1];
    }
}

// ---------------- router + top-k + beta weights + inlined group build ----------------
__global__ void router_kernel(const float* __restrict__ router_w,
                              const float* __restrict__ router_b,
                              const float* __restrict__ beta_w,
                              const float* __restrict__ beta_b) {
    int b = blockIdx.x;
    __shared__ float tmp_s[512];
    __shared__ float logit[32];
    __shared__ float al[Ee], be[Ee];
    __shared__ int sel_i[Kk];
    __shared__ float w_s[Kk * Tt];
    int tid = threadIdx.x;
    for (int c = tid; c < 512; c += 256) tmp_s[c] = g_tmp[b * Cc + c];
    __syncthreads();
    int w = tid >> 5, lane = tid & 31;
    for (int r = w; r < 30; r += 8) {
        const float* wr; float bias;
        if (r < Ee) { wr = router_w + r * 512; bias = router_b[r]; }
        else { wr = beta_w + (r - Ee) * 512; bias = beta_b[r - Ee]; }
        float s = 0.f;
        for (int c = lane; c < 512; c += 32) s += wr[c] * tmp_s[c];
#pragma unroll
        for (int o = 16; o > 0; o >>= 1) s += __shfl_down_sync(0xffffffffu, s, o);
        if (lane == 0) logit[r] = s + bias;
    }
    __syncthreads();
    if (tid < Ee) {
        al[tid] = softplus_f(logit[Ee + 2 * tid]) + 1e-6f;
        be[tid] = softplus_f(logit[Ee + 2 * tid + 1]) + 1e-6f;
    }
    if (tid == 0) {
        float m = logit[0];
        for (int e = 1; e < Ee; e++) m = fmaxf(m, logit[e]);
        float pe[Ee]; float s = 0.f;
        for (int e = 0; e < Ee; e++) { pe[e] = expf(logit[e] - m); s += pe[e]; }
        float invs = 1.0f / s;
        for (int e = 0; e < Ee; e++) pe[e] *= invs;
        bool used[Ee] = {};
        float psum = 0.f; float sp[Kk];
        for (int kk = 0; kk < Kk; kk++) {
            int best = 0; float bv = -1.f;
            for (int e = 0; e < Ee; e++)
                if (!used[e] && pe[e] > bv) { bv = pe[e]; best = e; }
            used[best] = true; sel_i[kk] = best; sp[kk] = bv; psum += bv;
        }
        float inv = 1.0f / (psum + 1e-8f);
        for (int kk = 0; kk < Kk; kk++) {
            int e = sel_i[kk];
            g_topk_i[b * Kk + kk] = e;
            g_topk_p[b * Kk + kk] = sp[kk] * inv;
            // inlined group build (order nondeterministic; consumers order-invariant)
            int slot = atomicAdd(&g_cnt[e], 1);
            g_glist[e * 256 + slot] = b * Kk + kk;
        }
    }
    __syncthreads();
    for (int i = tid; i < Kk * Tt; i += 256) {
        int kk = i / Tt, t = i % Tt;
        int e = sel_i[kk];
        float a = al[e], bb = be[e];
        float tt = (float)t / 59.0f;
        float lt = logf(tt + 1e-12f);
        float l1 = logf(1.0f - tt + 1e-12f);
        float norm = lgammaf(a) + lgammaf(bb) - lgammaf(a + bb);
        w_s[i] = expf((a - 1.0f) * lt + (bb - 1.0f) * l1 - norm);
    }
    __syncthreads();
    if (tid < Kk) {
        float m = 0.f;
        for (int t = 0; t < Tt; t++) m = fmaxf(m, w_s[tid * Tt + t]);
        float inv = 1.0f / (m + 1e-8f);
        float s = 0.f;
        for (int t = 0; t < Tt; t++) {
            float v = w_s[tid * Tt + t] * inv;
            g_tw[(b * Kk + tid) * Tt + t] = v;
            s += v;
        }
        g_sw[b * Kk + tid] = s;
    }
}

// ---------------- layer1: fp16 tensor cores, M=64 N=128 tiles, cp.async double-buffered ----------------
// grid (2, B*K), 256 threads (8 warps), dynamic smem.
// smem layout: As 2x(64x72) halfs @0 ; Bs 2x(128x72) halfs @18432 ; tw 64f @55296 ; red 4x132f @55552
#define L1_SMEM 57664
__global__ void layer1_mma_kernel(const float* __restrict__ b1) {
    extern __shared__ char sm[];
    __half* As = (__half*)sm;
    __half* Bs = (__half*)(sm + 18432);
    float* tw_s = (float*)(sm + 55296);
    float* red = (float*)(sm + 55552);
    int bk = blockIdx.y;
    int b = bk / Kk;
    int n0blk = blockIdx.x * 128;
    int e = g_topk_i[bk];
    int tid = threadIdx.x;
    int warp = tid >> 5, lane = tid & 31;
    int mw = warp >> 1, nw = warp & 1;

    if (tid < 64) tw_s[tid] = (tid < Tt) ? g_tw[bk * Tt + tid] : 0.0f;

    const __half* Ap = g_dh + (long)b * (Tt * Cc);
    const __half* Wp = g_w1h + (long)e * (256 * Cc) + (long)n0blk * Cc;

    auto issue = [&](int ch, int buf) {
        int kb = ch * 64;
        // A: 64 rows x 64 k = 512 x 16B, 2 per thread
#pragma unroll
        for (int it = 0; it < 2; it++) {
            int idx = it * 256 + tid;
            int row = idx >> 3, ub = (idx & 7) * 8;
            const __half* a = (row < Tt) ? (Ap + row * Cc + kb + ub) : Ap;
            cp16(smem_u32(As + buf * 4608 + row * 72 + ub), a, row < Tt ? 16 : 0);
        }
        // B: 128 rows x 64 k = 1024 x 16B, 4 per thread
#pragma unroll
        for (int it = 0; it < 4; it++) {
            int idx = it * 256 + tid;
            int row = idx >> 3, ub = (idx & 7) * 8;
            cp16(smem_u32(Bs + buf * 9216 + row * 72 + ub), Wp + row * Cc + kb + ub, 16);
        }
        cp_commit();
    };

    float acc[8][4] = {};
    issue(0, 0);
    for (int ch = 0; ch < 8; ch++) {
        int cur = ch & 1;
        if (ch < 7) { issue(ch + 1, cur ^ 1); cp_wait<1>(); }
        else { cp_wait<0>(); }
        __syncthreads();
#pragma unroll
        for (int ks = 0; ks < 4; ks++) {
            uint32_t a[4];
            int arow = mw * 16 + (lane & 15);
            int acol = ks * 16 + (lane >> 4) * 8;
            ldm_x4(a, smem_u32(As + cur * 4608 + arow * 72 + acol));
            uint32_t bf[16];
#pragma unroll
            for (int half = 0; half < 4; half++) {
                int nbase = nw * 64 + half * 16;
                int grp = lane >> 3, l8 = lane & 7;
                int nrow = nbase + (grp >> 1) * 8 + l8;
                int kcol = ks * 16 + (grp & 1) * 8;
                ldm_x4(bf + half * 4, smem_u32(Bs + cur * 9216 + nrow * 72 + kcol));
            }
#pragma unroll
            for (int j = 0; j < 8; j++) mma16816(acc[j], a, bf + j * 2);
        }
        __syncthreads();
    }
    int g = lane >> 2, t4 = lane & 3;
    int r0 = mw * 16 + g, r1 = r0 + 8;
    float w0 = tw_s[r0], w1 = tw_s[r1];
#pragma unroll
    for (int j = 0; j < 8; j++) {
        int nc0 = nw * 64 + j * 8 + t4 * 2;
        float bias0 = b1[e * 256 + n0blk + nc0];
        float bias1 = b1[e * 256 + n0blk + nc0 + 1];
        float s0 = w0 * fmaxf(acc[j][0] + bias0, 0.f) + w1 * fmaxf(acc[j][2] + bias0, 0.f);
        float s1 = w0 * fmaxf(acc[j][1] + bias1, 0.f) + w1 * fmaxf(acc[j][3] + bias1, 0.f);
#pragma unroll
        for (int o = 16; o >= 4; o >>= 1) {
            s0 += __shfl_down_sync(0xffffffffu, s0, o);
            s1 += __shfl_down_sync(0xffffffffu, s1, o);
        }
        if (g == 0) {
            red[mw * 132 + nc0] = s0;
            red[mw * 132 + nc0 + 1] = s1;
        }
    }
    __syncthreads();
    if (tid < 128) {
        float p = red[tid] + red[132 + tid] + red[264 + tid] + red[396 + tid];
        g_pooled[bk * 256 + n0blk + tid] = p;
    }
}

// ---------------- layer2: expert-grouped GEMM ----------------
__global__ void layer2_kernel(const float* __restrict__ w2,
                              const float* __restrict__ b2) {
    int nt = blockIdx.x, mt = blockIdx.y, e = blockIdx.z;
    int cnt = g_cnt[e];
    if (mt * 32 >= cnt) return;
    __shared__ float P[32 * 260];
    __shared__ float Ws[64 * 65];
    __shared__ int prs[32];
    int tid = threadIdx.x;
    int rows = cnt - mt * 32; if (rows > 32) rows = 32;
    if (tid < 32) prs[tid] = (tid < rows) ? g_glist[e * 256 + mt * 32 + tid] : -1;
    __syncthreads();
#pragma unroll
    for (int r = 0; r < 8; r++) {
        int fi = r * 256 + tid;
        int row = fi >> 6, c4 = (fi & 63) * 4;
        float4 v = make_float4(0.f, 0.f, 0.f, 0.f);
        int p = prs[row];
        if (p >= 0) v = *(const float4*)&g_pooled[p * 256 + c4];
        *(float4*)&P[row * 260 + c4] = v;
    }
    int nn = tid & 31, mg = tid >> 5;
    float acc[4][2] = {};
    for (int q = 0; q < 4; q++) {
        __syncthreads();
#pragma unroll
        for (int r = 0; r < 16; r++) {
            int fi = r * 256 + tid;
            int n = fi >> 6, kc = fi & 63;
            Ws[n * 65 + kc] = w2[(e * 512 + nt * 64 + n) * 256 + q * 64 + kc];
        }
        __syncthreads();
#pragma unroll 4
        for (int kc = 0; kc < 64; kc++) {
            float w0 = Ws[nn * 65 + kc];
            float w1 = Ws[(nn + 32) * 65 + kc];
#pragma unroll
            for (int mi = 0; mi < 4; mi++) {
                float pv = P[(mg + mi * 8) * 260 + q * 64 + kc];
                acc[mi][0] += pv * w0;
                acc[mi][1] += pv * w1;
            }
        }
    }
#pragma unroll
    for (int mi = 0; mi < 4; mi++) {
        int row = mg + mi * 8;
        int p = prs[row];
        if (p >= 0) {
            float sw = g_sw[p];
            int cc0 = nt * 64 + nn, cc1 = cc0 + 32;
            g_perexp[p * 512 + cc0] = acc[mi][0] + sw * b2[e * 512 + cc0];
            g_perexp[p * 512 + cc1] = acc[mi][1] + sw * b2[e * 512 + cc1];
        }
    }
}

// ---------------- combine + LayerNorm ----------------
__global__ void ln_kernel(const float* __restrict__ ln_g,
                          const float* __restrict__ ln_b,
                          float* __restrict__ out) {
    int b = blockIdx.x, tid = threadIdx.x;
    __shared__ float red[18];
    float y0 = 0.f, y1 = 0.f;
#pragma unroll
    for (int kk = 0; kk < Kk; kk++) {
        float p = g_topk_p[b * Kk + kk];
        const float* pe = g_perexp + (b * Kk + kk) * 512;
        y0 += p * pe[tid];
        y1 += p * pe[tid + 256];
    }
    float s = y0 + y1, sq = y0 * y0 + y1 * y1;
    int w = tid >> 5, lane = tid & 31;
#pragma unroll
    for (int o = 16; o > 0; o >>= 1) {
        s += __shfl_down_sync(0xffffffffu, s, o);
        sq += __shfl_down_sync(0xffffffffu, sq, o);
    }
    if (lane == 0) { red[w] = s; red[8 + w] = sq; }
    __syncthreads();
    if (tid == 0) {
        float S = 0.f, SQ = 0.f;
        for (int i = 0; i < 8; i++) { S += red[i]; SQ += red[8 + i]; }
        red[16] = S; red[17] = SQ;
    }
    __syncthreads();
    float mean = red[16] * (1.0f / 512.0f);
    float var = red[17] * (1.0f / 512.0f) - mean * mean;
    float rstd = rsqrtf(var + 1e-5f);
    out[b * Cc + tid] = (y0 - mean) * rstd * ln_g[tid] + ln_b[tid];
    out[b * Cc + tid + 256] = (y1 - mean) * rstd * ln_g[tid + 256] + ln_b[tid + 256];
}

// ---------------- launch ----------------
extern "C" void kernel_launch(void* const* d_in, const int* in_sizes, int n_in,
                              void* d_out, int out_size) {
    const float* qst = (const float*)d_in[0];
    const float* data = (const float*)d_in[1];
    const float* ipw = (const float*)d_in[2];
    const float* ipb = (const float*)d_in[3];
    const float* opw = (const float*)d_in[4];
    const float* opb = (const float*)d_in[5];
    const float* rw  = (const float*)d_in[6];
    const float* rb  = (const float*)d_in[7];
    const float* bw  = (const float*)d_in[8];
    const float* bb  = (const float*)d_in[9];
    const float* w1  = (const float*)d_in[10];
    const float* b1  = (const float*)d_in[11];
    const float* w2  = (const float*)d_in[12];
    const float* b2  = (const float*)d_in[13];
    const float* lng = (const float*)d_in[14];
    const float* lnb = (const float*)d_in[15];
    float* out = (float*)d_out;

    static bool attr_done = false;
    if (!attr_done) {
        cudaFuncSetAttribute(layer1_mma_kernel,
                             cudaFuncAttributeMaxDynamicSharedMemorySize, L1_SMEM);
        attr_done = true;
    }

    prep_kernel<<<(Bb * Tt * Cc + 255) / 256, 256>>>(data, w1);
    proj_q_kernel<<<dim3(8, 8), 256>>>(qst, ipw, ipb);
    rk_kernel<<<dim3(8, 8, 8), 256>>>(ipw);
    attn_kernel<<<Bb, 256>>>(data, ipb);
    ctx_kernel<<<dim3(8, 8), 256>>>(ipw, ipb);
    proj_tmp_kernel<<<dim3(8, 8), 256>>>(opw, opb);
    router_kernel<<<Bb, 256>>>(rw, rb, bw, bb);
    layer1_mma_kernel<<<dim3(2, Bb * Kk), 256, L1_SMEM>>>(b1);
    layer2_kernel<<<dim3(8, 8, Ee), 256>>>(w2, b2);
    ln_kernel<<<Bb, 256>>>(lng, lnb, out);
}